// round 1
// baseline (speedup 1.0000x reference)
#include <cuda_runtime.h>
#include <math.h>

#define B_   2
#define S_   4096
#define DM_  1024
#define DK_  64

// Scratch for projected q, k, v  (2 MB each — __device__ globals per allocation rules)
__device__ float g_q[B_ * S_ * DK_];
__device__ float g_k[B_ * S_ * DK_];
__device__ float g_v[B_ * S_ * DK_];

// ---------------------------------------------------------------------------
// Projection GEMM:  C[m][n] = sum_k A[m][k] * W[n][k] + bias[n]
// A: [8192, 1024]  W: [64, 1024]  C: [8192, 64]
// Block: 64(M) x 64(N), BK=16, 64 threads, 8x8 microtile (FMA:LDS byte = 1:1)
// grid = (128, 1, 3); z selects Q/K/V projection.
// ---------------------------------------------------------------------------
__global__ __launch_bounds__(64)
void proj_kernel(const float* __restrict__ Qin, const float* __restrict__ Kin,
                 const float* __restrict__ Vin,
                 const float* __restrict__ Wq, const float* __restrict__ Wk,
                 const float* __restrict__ Wv,
                 const float* __restrict__ bq, const float* __restrict__ bk,
                 const float* __restrict__ bv)
{
    __shared__ float As[16 * 68];   // As[kk][r], stride 68 (2-way write conflict max)
    __shared__ float Ws[16 * 68];   // Ws[kk][n]

    const int which = blockIdx.z;
    const float* A    = (which == 0) ? Qin : (which == 1) ? Kin : Vin;
    const float* W    = (which == 0) ? Wq  : (which == 1) ? Wk  : Wv;
    const float* bias = (which == 0) ? bq  : (which == 1) ? bk  : bv;
    float*       C    = (which == 0) ? g_q : (which == 1) ? g_k : g_v;

    const int tid = threadIdx.x;
    const int tx  = tid & 7;    // N dir, 8 positions * 8 cols
    const int ty  = tid >> 3;   // M dir, 8 positions * 8 rows
    const int m0  = blockIdx.x * 64;

    float acc[8][8];
#pragma unroll
    for (int i = 0; i < 8; i++)
#pragma unroll
        for (int j = 0; j < 8; j++) acc[i][j] = 0.f;

    for (int kb = 0; kb < DM_; kb += 16) {
        // Load A tile 64x16 (coalesced float4 global reads, transposed smem store)
#pragma unroll
        for (int e = tid; e < 256; e += 64) {
            const int r = e >> 2, c4 = e & 3;
            const float4 v = *(const float4*)(A + (size_t)(m0 + r) * DM_ + kb + c4 * 4);
            As[(c4 * 4 + 0) * 68 + r] = v.x;
            As[(c4 * 4 + 1) * 68 + r] = v.y;
            As[(c4 * 4 + 2) * 68 + r] = v.z;
            As[(c4 * 4 + 3) * 68 + r] = v.w;
        }
        // Load W tile 64x16
#pragma unroll
        for (int e = tid; e < 256; e += 64) {
            const int n = e >> 2, c4 = e & 3;
            const float4 v = *(const float4*)(W + (size_t)n * DM_ + kb + c4 * 4);
            Ws[(c4 * 4 + 0) * 68 + n] = v.x;
            Ws[(c4 * 4 + 1) * 68 + n] = v.y;
            Ws[(c4 * 4 + 2) * 68 + n] = v.z;
            Ws[(c4 * 4 + 3) * 68 + n] = v.w;
        }
        __syncthreads();

#pragma unroll
        for (int kk = 0; kk < 16; kk++) {
            const float4 a0 = *(const float4*)(As + kk * 68 + ty * 8);
            const float4 a1 = *(const float4*)(As + kk * 68 + ty * 8 + 4);
            const float4 b0 = *(const float4*)(Ws + kk * 68 + tx * 8);
            const float4 b1 = *(const float4*)(Ws + kk * 68 + tx * 8 + 4);
            const float af[8] = {a0.x, a0.y, a0.z, a0.w, a1.x, a1.y, a1.z, a1.w};
            const float bf[8] = {b0.x, b0.y, b0.z, b0.w, b1.x, b1.y, b1.z, b1.w};
#pragma unroll
            for (int i = 0; i < 8; i++)
#pragma unroll
                for (int j = 0; j < 8; j++)
                    acc[i][j] = fmaf(af[i], bf[j], acc[i][j]);
        }
        __syncthreads();
    }

#pragma unroll
    for (int i = 0; i < 8; i++) {
        const size_t row = (size_t)(m0 + ty * 8 + i);
#pragma unroll
        for (int j4 = 0; j4 < 2; j4++) {
            float4 o;
            o.x = acc[i][j4 * 4 + 0] + bias[tx * 8 + j4 * 4 + 0];
            o.y = acc[i][j4 * 4 + 1] + bias[tx * 8 + j4 * 4 + 1];
            o.z = acc[i][j4 * 4 + 2] + bias[tx * 8 + j4 * 4 + 2];
            o.w = acc[i][j4 * 4 + 3] + bias[tx * 8 + j4 * 4 + 3];
            *(float4*)(C + row * DK_ + tx * 8 + j4 * 4) = o;
        }
    }
}

// ---------------------------------------------------------------------------
// Flash attention:  per block = 64 q-rows of one batch; loop 64-key tiles.
// 256 threads, tx = k/d column group (16), ty = q row group (16), 4x4 microtiles.
// smem: qs[d][q] (transposed), ks[d][k] (transposed), vs[k][d], ps[k][q] (swizzled)
// ---------------------------------------------------------------------------
#define LDP 68   // ps stride (floats)

__global__ __launch_bounds__(256)
void attn_kernel(const int* __restrict__ mask, float* __restrict__ out)
{
    extern __shared__ float sm[];
    float* qs = sm;                     // 64*64
    float* ks = sm + 4096;              // 64*64
    float* vs = sm + 8192;              // 64*64
    float* ps = sm + 12288;             // 64*LDP

    const int b   = blockIdx.y;
    const int q0  = blockIdx.x * 64;
    const int tid = threadIdx.x;
    const int tx  = tid & 15;
    const int ty  = tid >> 4;

    // Load q tile transposed: qs[d][r] = g_q[b, q0+r, d].
    // r-fastest mapping: conflict-free STS (bank = r % 32, lanes span 32 rows).
    {
        const float* gq = g_q + ((size_t)b * S_ + q0) * DK_;
        for (int e = tid; e < 1024; e += 256) {
            const int c4 = e >> 6, r = e & 63;
            const float4 v = *(const float4*)(gq + r * DK_ + c4 * 4);
            qs[(c4 * 4 + 0) * 64 + r] = v.x;
            qs[(c4 * 4 + 1) * 64 + r] = v.y;
            qs[(c4 * 4 + 2) * 64 + r] = v.z;
            qs[(c4 * 4 + 3) * 64 + r] = v.w;
        }
    }

    float acc[4][4];
    float mi[4], li[4];
#pragma unroll
    for (int i = 0; i < 4; i++) {
        mi[i] = -1e30f;
        li[i] = 0.f;
#pragma unroll
        for (int j = 0; j < 4; j++) acc[i][j] = 0.f;
    }

    const float inv_sqrt_dk = 0.125f;  // 1/sqrt(64)

    for (int kt = 0; kt < S_ / 64; kt++) {
        const int k0 = kt * 64;
        __syncthreads();   // prev iteration's PV done before overwriting ks/vs

        // Load k tile transposed (conflict-free STS), v tile natural (coalesced)
        {
            const float* gk = g_k + ((size_t)b * S_ + k0) * DK_;
            const float* gv = g_v + ((size_t)b * S_ + k0) * DK_;
            for (int e = tid; e < 1024; e += 256) {
                const int c4 = e >> 6, r = e & 63;
                const float4 v = *(const float4*)(gk + r * DK_ + c4 * 4);
                ks[(c4 * 4 + 0) * 64 + r] = v.x;
                ks[(c4 * 4 + 1) * 64 + r] = v.y;
                ks[(c4 * 4 + 2) * 64 + r] = v.z;
                ks[(c4 * 4 + 3) * 64 + r] = v.w;
            }
            for (int e = tid; e < 1024; e += 256) {
                const int r = e >> 4, c4 = e & 15;
                *(float4*)(vs + r * 64 + c4 * 4) = *(const float4*)(gv + r * DK_ + c4 * 4);
            }
        }
        __syncthreads();

        // Scores: s[i][j] = sum_d q[q0+ty*4+i][d] * k[k0+tx*4+j][d]
        float s[4][4];
#pragma unroll
        for (int i = 0; i < 4; i++)
#pragma unroll
            for (int j = 0; j < 4; j++) s[i][j] = 0.f;

#pragma unroll 4
        for (int dd = 0; dd < 64; dd++) {
            const float4 qa = *(const float4*)(qs + dd * 64 + (ty << 2));
            const float4 kb = *(const float4*)(ks + dd * 64 + (tx << 2));
            const float af[4] = {qa.x, qa.y, qa.z, qa.w};
            const float bf[4] = {kb.x, kb.y, kb.z, kb.w};
#pragma unroll
            for (int i = 0; i < 4; i++)
#pragma unroll
                for (int j = 0; j < 4; j++)
                    s[i][j] = fmaf(af[i], bf[j], s[i][j]);
        }

        // Mask + online softmax (row groups = 16 tx lanes, butterfly reductions)
#pragma unroll
        for (int i = 0; i < 4; i++) {
            const int4 mv = *(const int4*)(mask +
                ((size_t)b * S_ + (q0 + ty * 4 + i)) * S_ + k0 + tx * 4);
            const float m0f = (float)mv.x, m1f = (float)mv.y,
                        m2f = (float)mv.z, m3f = (float)mv.w;
            s[i][0] = s[i][0] * inv_sqrt_dk * m0f - 1e9f * (1.f - m0f);
            s[i][1] = s[i][1] * inv_sqrt_dk * m1f - 1e9f * (1.f - m1f);
            s[i][2] = s[i][2] * inv_sqrt_dk * m2f - 1e9f * (1.f - m2f);
            s[i][3] = s[i][3] * inv_sqrt_dk * m3f - 1e9f * (1.f - m3f);

            float rm = fmaxf(fmaxf(s[i][0], s[i][1]), fmaxf(s[i][2], s[i][3]));
            rm = fmaxf(rm, __shfl_xor_sync(0xffffffffu, rm, 1));
            rm = fmaxf(rm, __shfl_xor_sync(0xffffffffu, rm, 2));
            rm = fmaxf(rm, __shfl_xor_sync(0xffffffffu, rm, 4));
            rm = fmaxf(rm, __shfl_xor_sync(0xffffffffu, rm, 8));

            const float mnew = fmaxf(mi[i], rm);
            const float sc   = __expf(mi[i] - mnew);
            float rs = 0.f;
#pragma unroll
            for (int j = 0; j < 4; j++) {
                s[i][j] = __expf(s[i][j] - mnew);
                rs += s[i][j];
            }
            rs += __shfl_xor_sync(0xffffffffu, rs, 1);
            rs += __shfl_xor_sync(0xffffffffu, rs, 2);
            rs += __shfl_xor_sync(0xffffffffu, rs, 4);
            rs += __shfl_xor_sync(0xffffffffu, rs, 8);

            li[i] = li[i] * sc + rs;
            mi[i] = mnew;
#pragma unroll
            for (int j = 0; j < 4; j++) acc[i][j] *= sc;
        }

        // Stage P transposed + swizzled: ps[k][ ((q>>2) ^ (k>>2))*4 + (q&3) ]
#pragma unroll
        for (int j = 0; j < 4; j++) {
            const int k   = tx * 4 + j;
            const int swz = ((ty ^ tx) << 2);
#pragma unroll
            for (int i = 0; i < 4; i++)
                ps[k * LDP + swz + i] = s[i][j];
        }
        __syncthreads();

        // acc += P @ V
#pragma unroll 4
        for (int kk = 0; kk < 64; kk++) {
            const float4 pa = *(const float4*)(ps + kk * LDP + ((ty ^ (kk >> 2)) << 2));
            const float4 vb = *(const float4*)(vs + kk * 64 + (tx << 2));
            const float pf[4] = {pa.x, pa.y, pa.z, pa.w};
            const float vf[4] = {vb.x, vb.y, vb.z, vb.w};
#pragma unroll
            for (int i = 0; i < 4; i++)
#pragma unroll
                for (int j = 0; j < 4; j++)
                    acc[i][j] = fmaf(pf[i], vf[j], acc[i][j]);
        }
    }

    // Epilogue: y = acc / l
    float* gout = out + ((size_t)b * S_ + q0) * DK_;
#pragma unroll
    for (int i = 0; i < 4; i++) {
        const float inv = 1.f / li[i];
        float4 o;
        o.x = acc[i][0] * inv;
        o.y = acc[i][1] * inv;
        o.z = acc[i][2] * inv;
        o.w = acc[i][3] * inv;
        *(float4*)(gout + (ty * 4 + i) * DK_ + tx * 4) = o;
    }
}

// ---------------------------------------------------------------------------
extern "C" void kernel_launch(void* const* d_in, const int* in_sizes, int n_in,
                              void* d_out, int out_size)
{
    const float* Q    = (const float*)d_in[0];
    const float* K    = (const float*)d_in[1];
    const float* V    = (const float*)d_in[2];
    const int*   mask = (const int*)  d_in[3];
    const float* Wq   = (const float*)d_in[4];
    const float* bq   = (const float*)d_in[5];
    const float* Wk   = (const float*)d_in[6];
    const float* bk   = (const float*)d_in[7];
    const float* Wv   = (const float*)d_in[8];
    const float* bv   = (const float*)d_in[9];
    float* out = (float*)d_out;

    // Projections: q,k,v = X @ W^T + b
    dim3 pgrid((B_ * S_) / 64, 1, 3);
    proj_kernel<<<pgrid, 64>>>(Q, K, V, Wq, Wk, Wv, bq, bk, bv);

    // Attention (dynamic smem 65 KB: qs+ks+vs 48 KB + ps 17 KB)
    const int smem_bytes = (12288 + 64 * LDP) * (int)sizeof(float);  // 66560
    cudaFuncSetAttribute(attn_kernel,
                         cudaFuncAttributeMaxDynamicSharedMemorySize, smem_bytes);
    attn_kernel<<<dim3(S_ / 64, B_), 256, smem_bytes>>>(mask, out);
}

// round 3
// speedup vs baseline: 2.5421x; 2.5421x over previous
#include <cuda_runtime.h>
#include <cuda_bf16.h>
#include <cstdint>

#define B_   2
#define S_   4096
#define DM_  1024
#define DK_  64

// ===========================================================================
// Scratch (__device__ globals per allocation rules)
// ===========================================================================
__device__ __nv_bfloat16 g_qh[B_ * S_ * DK_];
__device__ __nv_bfloat16 g_ql[B_ * S_ * DK_];
__device__ __nv_bfloat16 g_kh[B_ * S_ * DK_];
__device__ __nv_bfloat16 g_kl[B_ * S_ * DK_];
__device__ __nv_bfloat16 g_vth[B_ * DK_ * S_];   // V^T  [b][d][s]
__device__ __nv_bfloat16 g_vtl[B_ * DK_ * S_];
__device__ float g_pacc[2][B_ * S_ * DK_];       // per-split unnormalized O
__device__ float g_pl[2][B_ * S_];               // per-split softmax denominators

__device__ __forceinline__ uint32_t smem_to_u32(const void* p) {
    uint32_t a;
    asm("{ .reg .u64 t; cvta.to.shared.u64 t, %1; cvt.u32.u64 %0, t; }" : "=r"(a) : "l"(p));
    return a;
}
__device__ __forceinline__ uint32_t pack_bf16(__nv_bfloat16 a, __nv_bfloat16 b) {
    return (uint32_t)__bfloat16_as_ushort(a) | ((uint32_t)__bfloat16_as_ushort(b) << 16);
}
__device__ __forceinline__ void mma_bf16(float c[4], const uint32_t a[4],
                                         uint32_t b0, uint32_t b1) {
    asm volatile("mma.sync.aligned.m16n8k16.row.col.f32.bf16.bf16.f32 "
        "{%0,%1,%2,%3}, {%4,%5,%6,%7}, {%8,%9}, {%0,%1,%2,%3};"
        : "+f"(c[0]), "+f"(c[1]), "+f"(c[2]), "+f"(c[3])
        : "r"(a[0]), "r"(a[1]), "r"(a[2]), "r"(a[3]), "r"(b0), "r"(b1));
}
__device__ __forceinline__ void ldsm4(uint32_t r[4], uint32_t addr) {
    asm volatile("ldmatrix.sync.aligned.m8n8.x4.shared.b16 {%0,%1,%2,%3}, [%4];"
        : "=r"(r[0]), "=r"(r[1]), "=r"(r[2]), "=r"(r[3]) : "r"(addr));
}

// ===========================================================================
// Projection GEMM (fp32): C = A @ W^T + bias, epilogue emits bf16 hi/lo pairs.
// which: 0->q (g_qh/g_ql), 1->k (g_kh/g_kl), 2->v transposed (g_vth/g_vtl)
// ===========================================================================
__global__ __launch_bounds__(64)
void proj_kernel(const float* __restrict__ Qin, const float* __restrict__ Kin,
                 const float* __restrict__ Vin,
                 const float* __restrict__ Wq, const float* __restrict__ Wk,
                 const float* __restrict__ Wv,
                 const float* __restrict__ bq, const float* __restrict__ bk,
                 const float* __restrict__ bv)
{
    __shared__ float As[16 * 68];
    __shared__ float Ws[16 * 68];

    const int which = blockIdx.z;
    const float* A    = (which == 0) ? Qin : (which == 1) ? Kin : Vin;
    const float* W    = (which == 0) ? Wq  : (which == 1) ? Wk  : Wv;
    const float* bias = (which == 0) ? bq  : (which == 1) ? bk  : bv;

    const int tid = threadIdx.x;
    const int tx  = tid & 7;
    const int ty  = tid >> 3;
    const int m0  = blockIdx.x * 64;

    float acc[8][8];
#pragma unroll
    for (int i = 0; i < 8; i++)
#pragma unroll
        for (int j = 0; j < 8; j++) acc[i][j] = 0.f;

    for (int kb = 0; kb < DM_; kb += 16) {
#pragma unroll
        for (int e = tid; e < 256; e += 64) {
            const int r = e >> 2, c4 = e & 3;
            const float4 v = *(const float4*)(A + (size_t)(m0 + r) * DM_ + kb + c4 * 4);
            As[(c4 * 4 + 0) * 68 + r] = v.x;
            As[(c4 * 4 + 1) * 68 + r] = v.y;
            As[(c4 * 4 + 2) * 68 + r] = v.z;
            As[(c4 * 4 + 3) * 68 + r] = v.w;
        }
#pragma unroll
        for (int e = tid; e < 256; e += 64) {
            const int n = e >> 2, c4 = e & 3;
            const float4 v = *(const float4*)(W + (size_t)n * DM_ + kb + c4 * 4);
            Ws[(c4 * 4 + 0) * 68 + n] = v.x;
            Ws[(c4 * 4 + 1) * 68 + n] = v.y;
            Ws[(c4 * 4 + 2) * 68 + n] = v.z;
            Ws[(c4 * 4 + 3) * 68 + n] = v.w;
        }
        __syncthreads();

#pragma unroll
        for (int kk = 0; kk < 16; kk++) {
            const float4 a0 = *(const float4*)(As + kk * 68 + ty * 8);
            const float4 a1 = *(const float4*)(As + kk * 68 + ty * 8 + 4);
            const float4 b0 = *(const float4*)(Ws + kk * 68 + tx * 8);
            const float4 b1 = *(const float4*)(Ws + kk * 68 + tx * 8 + 4);
            const float af[8] = {a0.x, a0.y, a0.z, a0.w, a1.x, a1.y, a1.z, a1.w};
            const float bf[8] = {b0.x, b0.y, b0.z, b0.w, b1.x, b1.y, b1.z, b1.w};
#pragma unroll
            for (int i = 0; i < 8; i++)
#pragma unroll
                for (int j = 0; j < 8; j++)
                    acc[i][j] = fmaf(af[i], bf[j], acc[i][j]);
        }
        __syncthreads();
    }

    if (which != 2) {
        __nv_bfloat16* H = (which == 0) ? g_qh : g_kh;
        __nv_bfloat16* L = (which == 0) ? g_ql : g_kl;
#pragma unroll
        for (int i = 0; i < 8; i++) {
            const size_t r = (size_t)(m0 + ty * 8 + i);
            uint32_t hw[4], lw[4];
#pragma unroll
            for (int p = 0; p < 4; p++) {
                const float o0 = acc[i][2 * p]     + bias[tx * 8 + 2 * p];
                const float o1 = acc[i][2 * p + 1] + bias[tx * 8 + 2 * p + 1];
                const __nv_bfloat16 h0 = __float2bfloat16(o0);
                const __nv_bfloat16 h1 = __float2bfloat16(o1);
                hw[p] = pack_bf16(h0, h1);
                lw[p] = pack_bf16(__float2bfloat16(o0 - __bfloat162float(h0)),
                                  __float2bfloat16(o1 - __bfloat162float(h1)));
            }
            *(uint4*)((char*)(H + r * DK_ + tx * 8)) = make_uint4(hw[0], hw[1], hw[2], hw[3]);
            *(uint4*)((char*)(L + r * DK_ + tx * 8)) = make_uint4(lw[0], lw[1], lw[2], lw[3]);
        }
    } else {
#pragma unroll
        for (int i = 0; i < 8; i++) {
            const int r = m0 + ty * 8 + i;
            const int bb = r >> 12, ss = r & (S_ - 1);
#pragma unroll
            for (int j = 0; j < 8; j++) {
                const int col = tx * 8 + j;
                const float o = acc[i][j] + bias[col];
                const __nv_bfloat16 h = __float2bfloat16(o);
                const size_t off = ((size_t)(bb * DK_ + col)) * S_ + ss;
                g_vth[off] = h;
                g_vtl[off] = __float2bfloat16(o - __bfloat162float(h));
            }
        }
    }
}

// ===========================================================================
// mma.sync attention: 128-q CTA (8 warps x 16 rows), 64-key tiles, kv-split 2.
// 3-pass bf16 hi/lo on both GEMMs. P stays in registers (C-frag == A-frag).
// smem tiles XOR-swizzled at 16B granularity for conflict-free ldmatrix.
// ===========================================================================
__global__ __launch_bounds__(256)
void attn_mma_kernel(const int* __restrict__ mask)
{
    __shared__ __align__(16) __nv_bfloat16 s_kh[64 * 64];
    __shared__ __align__(16) __nv_bfloat16 s_kl[64 * 64];
    __shared__ __align__(16) __nv_bfloat16 s_vh[64 * 64];   // V^T tile: [d][key]
    __shared__ __align__(16) __nv_bfloat16 s_vl[64 * 64];

    const int tid  = threadIdx.x;
    const int wid  = tid >> 5;
    const int lane = tid & 31;
    const int grp  = lane >> 2;        // fragment row group 0..7
    const int qp   = (lane & 3) * 2;   // fragment col pair base

    const int b     = blockIdx.y;
    const int sp    = blockIdx.z;
    const int q0    = blockIdx.x * 128;
    const int kbase = sp * 2048;
    const int qrow0 = q0 + wid * 16;
    const size_t bS = (size_t)b * S_;

    const uint32_t a_kh = smem_to_u32(s_kh);
    const uint32_t a_kl = smem_to_u32(s_kl);
    const uint32_t a_vh = smem_to_u32(s_vh);
    const uint32_t a_vl = smem_to_u32(s_vl);

    // ---- Q fragments (hi/lo), loaded once from global. A-frag m16k16 layout:
    // reg0=(row,k) reg1=(row+8,k) reg2=(row,k+8) reg3=(row+8,k+8)
    uint32_t qh[4][4], ql[4][4];
    {
        const size_t r0 = (bS + qrow0 + grp) * DK_;
        const size_t r1 = r0 + 8 * DK_;
#pragma unroll
        for (int c = 0; c < 4; c++) {
            qh[c][0] = *(const uint32_t*)(g_qh + r0 + c * 16 + qp);
            qh[c][1] = *(const uint32_t*)(g_qh + r1 + c * 16 + qp);
            qh[c][2] = *(const uint32_t*)(g_qh + r0 + c * 16 + qp + 8);
            qh[c][3] = *(const uint32_t*)(g_qh + r1 + c * 16 + qp + 8);
            ql[c][0] = *(const uint32_t*)(g_ql + r0 + c * 16 + qp);
            ql[c][1] = *(const uint32_t*)(g_ql + r1 + c * 16 + qp);
            ql[c][2] = *(const uint32_t*)(g_ql + r0 + c * 16 + qp + 8);
            ql[c][3] = *(const uint32_t*)(g_ql + r1 + c * 16 + qp + 8);
        }
    }

    float O[32];
#pragma unroll
    for (int i = 0; i < 32; i++) O[i] = 0.f;
    float l0 = 0.f, l1 = 0.f;

    // ldmatrix lane addressing pieces (row within 8-row group, matrix id)
    const int lm_m = lane >> 3;        // matrix 0..3
    const int lm_i = lane & 7;         // row within matrix
    const int lm_rhalf = (lm_m >> 1) << 3;   // +8 rows for matrices 2,3
    const int lm_csel  = lm_m & 1;           // +1 chunk for matrices 1,3

    const size_t mrow0 = (bS + qrow0 + grp) * S_;
    const size_t mrow1 = mrow0 + (size_t)8 * S_;

    for (int t = 0; t < 32; t++) {
        const int k0 = kbase + t * 64;
        __syncthreads();

        // ---- fill smem tiles (16B-chunk XOR swizzle: chunk g -> g ^ (row&7))
        {
            const size_t krow = bS + k0;
#pragma unroll
            for (int idx = tid; idx < 512; idx += 256) {
                const int r = idx >> 3, g = idx & 7;
                const uint32_t off = (uint32_t)(r * 128 + ((g ^ (r & 7)) * 16));
                *(uint4*)((char*)s_kh + off) = *(const uint4*)(g_kh + (krow + r) * DK_ + g * 8);
                *(uint4*)((char*)s_kl + off) = *(const uint4*)(g_kl + (krow + r) * DK_ + g * 8);
                const size_t vsrc = ((size_t)(b * DK_ + r)) * S_ + k0 + g * 8;
                *(uint4*)((char*)s_vh + off) = *(const uint4*)(g_vth + vsrc);
                *(uint4*)((char*)s_vl + off) = *(const uint4*)(g_vtl + vsrc);
            }
        }
        __syncthreads();

        // ---- scores + softmax + P fragments (per 16-key chunk = 2 n8 tiles)
        uint32_t ph[4][4], pl[4][4];
#pragma unroll
        for (int nt2 = 0; nt2 < 4; nt2++) {
            float cA[4] = {0.f, 0.f, 0.f, 0.f};
            float cB[4] = {0.f, 0.f, 0.f, 0.f};
#pragma unroll
            for (int c = 0; c < 4; c++) {
                const int row = nt2 * 16 + lm_rhalf + lm_i;
                const uint32_t off = (uint32_t)(row * 128 + (((c * 2 + lm_csel) ^ (row & 7)) * 16));
                uint32_t bh[4], bl[4];
                ldsm4(bh, a_kh + off);
                ldsm4(bl, a_kl + off);
                mma_bf16(cA, qh[c], bh[0], bh[1]);
                mma_bf16(cA, qh[c], bl[0], bl[1]);
                mma_bf16(cA, ql[c], bh[0], bh[1]);
                mma_bf16(cB, qh[c], bh[2], bh[3]);
                mma_bf16(cB, qh[c], bl[2], bl[3]);
                mma_bf16(cB, ql[c], bh[2], bh[3]);
            }
            // tiles: keys [nt2*16, nt2*16+8) -> cA, [nt2*16+8, nt2*16+16) -> cB
#pragma unroll
            for (int half = 0; half < 2; half++) {
                float* cc = half ? cB : cA;
                const int col = k0 + nt2 * 16 + half * 8 + qp;
                const int2 mA = *(const int2*)(mask + mrow0 + col);
                const int2 mB = *(const int2*)(mask + mrow1 + col);
                const float p0 = mA.x ? __expf(cc[0] * 0.125f) : 0.f;
                const float p1 = mA.y ? __expf(cc[1] * 0.125f) : 0.f;
                const float p2 = mB.x ? __expf(cc[2] * 0.125f) : 0.f;
                const float p3 = mB.y ? __expf(cc[3] * 0.125f) : 0.f;
                l0 += p0 + p1;
                l1 += p2 + p3;
                const __nv_bfloat16 h0 = __float2bfloat16(p0), h1 = __float2bfloat16(p1);
                const __nv_bfloat16 h2 = __float2bfloat16(p2), h3 = __float2bfloat16(p3);
                ph[nt2][half * 2 + 0] = pack_bf16(h0, h1);   // wait: reg order fixed below
                ph[nt2][half * 2 + 1] = pack_bf16(h2, h3);
                pl[nt2][half * 2 + 0] = pack_bf16(__float2bfloat16(p0 - __bfloat162float(h0)),
                                                  __float2bfloat16(p1 - __bfloat162float(h1)));
                pl[nt2][half * 2 + 1] = pack_bf16(__float2bfloat16(p2 - __bfloat162float(h2)),
                                                  __float2bfloat16(p3 - __bfloat162float(h3)));
            }
        }
        // P A-frag reg order per kchunk: [0]=(row,klo) [1]=(row+8,klo) [2]=(row,khi) [3]=(row+8,khi)
        // (layout above already matches: half0 -> regs 0,1 ; half1 -> regs 2,3)

        // ---- O += P @ V^T  (two d8 tiles per ldmatrix pass)
#pragma unroll
        for (int dt2 = 0; dt2 < 4; dt2++) {
            float* oA = &O[dt2 * 8];
            float* oB = &O[dt2 * 8 + 4];
#pragma unroll
            for (int kc = 0; kc < 4; kc++) {
                const int row = dt2 * 16 + lm_rhalf + lm_i;
                const uint32_t off = (uint32_t)(row * 128 + (((kc * 2 + lm_csel) ^ (row & 7)) * 16));
                uint32_t bh[4], bl[4];
                ldsm4(bh, a_vh + off);
                ldsm4(bl, a_vl + off);
                mma_bf16(oA, ph[kc], bh[0], bh[1]);
                mma_bf16(oA, ph[kc], bl[0], bl[1]);
                mma_bf16(oA, pl[kc], bh[0], bh[1]);
                mma_bf16(oB, ph[kc], bh[2], bh[3]);
                mma_bf16(oB, ph[kc], bl[2], bl[3]);
                mma_bf16(oB, pl[kc], bh[2], bh[3]);
            }
        }
    }

    // ---- epilogue: reduce l across the quad, write partial O + l
    l0 += __shfl_xor_sync(0xffffffffu, l0, 1);
    l0 += __shfl_xor_sync(0xffffffffu, l0, 2);
    l1 += __shfl_xor_sync(0xffffffffu, l1, 1);
    l1 += __shfl_xor_sync(0xffffffffu, l1, 2);
    if ((lane & 3) == 0) {
        g_pl[sp][bS + qrow0 + grp]     = l0;
        g_pl[sp][bS + qrow0 + grp + 8] = l1;
    }
    float* dst0 = g_pacc[sp] + (bS + qrow0 + grp) * DK_;
    float* dst1 = dst0 + 8 * DK_;
#pragma unroll
    for (int dt = 0; dt < 8; dt++) {
        const int col = dt * 8 + qp;
        *(float2*)(dst0 + col) = make_float2(O[dt * 4 + 0], O[dt * 4 + 1]);
        *(float2*)(dst1 + col) = make_float2(O[dt * 4 + 2], O[dt * 4 + 3]);
    }
}

// ===========================================================================
// Merge the 2 kv-splits: y = (acc0 + acc1) / (l0 + l1)
// ===========================================================================
__global__ __launch_bounds__(256)
void merge_kernel(float* __restrict__ out)
{
    const int idx = blockIdx.x * 256 + threadIdx.x;
    const int r = idx >> 6;
    const float l = g_pl[0][r] + g_pl[1][r];
    out[idx] = (g_pacc[0][idx] + g_pacc[1][idx]) / l;
}

// ===========================================================================
extern "C" void kernel_launch(void* const* d_in, const int* in_sizes, int n_in,
                              void* d_out, int out_size)
{
    const float* Q    = (const float*)d_in[0];
    const float* K    = (const float*)d_in[1];
    const float* V    = (const float*)d_in[2];
    const int*   mask = (const int*)  d_in[3];
    const float* Wq   = (const float*)d_in[4];
    const float* bq   = (const float*)d_in[5];
    const float* Wk   = (const float*)d_in[6];
    const float* bk   = (const float*)d_in[7];
    const float* Wv   = (const float*)d_in[8];
    const float* bv   = (const float*)d_in[9];
    float* out = (float*)d_out;

    proj_kernel<<<dim3((B_ * S_) / 64, 1, 3), 64>>>(Q, K, V, Wq, Wk, Wv, bq, bk, bv);

    attn_mma_kernel<<<dim3(S_ / 128, B_, 2), 256>>>(mask);

    merge_kernel<<<(B_ * S_ * DK_) / 256, 256>>>(out);
}

// round 4
// speedup vs baseline: 3.4482x; 1.3564x over previous
#include <cuda_runtime.h>
#include <cuda_bf16.h>
#include <cstdint>

#define B_   2
#define S_   4096
#define DM_  1024
#define DK_  64

// ===========================================================================
// Scratch (__device__ globals per allocation rules)
// ===========================================================================
__device__ __nv_bfloat16 g_qh[B_ * S_ * DK_];
__device__ __nv_bfloat16 g_ql[B_ * S_ * DK_];
__device__ __nv_bfloat16 g_kh[B_ * S_ * DK_];
__device__ __nv_bfloat16 g_kl[B_ * S_ * DK_];
__device__ __nv_bfloat16 g_vh[B_ * S_ * DK_];    // row-major [b][s][d]
__device__ __nv_bfloat16 g_vl[B_ * S_ * DK_];
__device__ __nv_bfloat16 g_wh[3 * DK_ * DM_];    // pre-converted W hi/lo
__device__ __nv_bfloat16 g_wl[3 * DK_ * DM_];
__device__ float g_pacc[2][B_ * S_ * DK_];       // per-split unnormalized O
__device__ float g_pl[2][B_ * S_];               // per-split softmax denominators

__device__ __forceinline__ uint32_t smem_to_u32(const void* p) {
    uint32_t a;
    asm("{ .reg .u64 t; cvta.to.shared.u64 t, %1; cvt.u32.u64 %0, t; }" : "=r"(a) : "l"(p));
    return a;
}
__device__ __forceinline__ uint32_t pack_bf16(__nv_bfloat16 a, __nv_bfloat16 b) {
    return (uint32_t)__bfloat16_as_ushort(a) | ((uint32_t)__bfloat16_as_ushort(b) << 16);
}
// split two fp32 into packed bf16 hi word + residual lo word
__device__ __forceinline__ void split2(float a, float b, uint32_t& h, uint32_t& l) {
    const __nv_bfloat16 ha = __float2bfloat16(a);
    const __nv_bfloat16 hb = __float2bfloat16(b);
    h = pack_bf16(ha, hb);
    l = pack_bf16(__float2bfloat16(a - __bfloat162float(ha)),
                  __float2bfloat16(b - __bfloat162float(hb)));
}
__device__ __forceinline__ void mma_bf16(float c[4], const uint32_t a[4],
                                         uint32_t b0, uint32_t b1) {
    asm volatile("mma.sync.aligned.m16n8k16.row.col.f32.bf16.bf16.f32 "
        "{%0,%1,%2,%3}, {%4,%5,%6,%7}, {%8,%9}, {%0,%1,%2,%3};"
        : "+f"(c[0]), "+f"(c[1]), "+f"(c[2]), "+f"(c[3])
        : "r"(a[0]), "r"(a[1]), "r"(a[2]), "r"(a[3]), "r"(b0), "r"(b1));
}
__device__ __forceinline__ void ldsm4(uint32_t r[4], uint32_t addr) {
    asm volatile("ldmatrix.sync.aligned.m8n8.x4.shared.b16 {%0,%1,%2,%3}, [%4];"
        : "=r"(r[0]), "=r"(r[1]), "=r"(r[2]), "=r"(r[3]) : "r"(addr));
}
__device__ __forceinline__ void ldsm4t(uint32_t r[4], uint32_t addr) {
    asm volatile("ldmatrix.sync.aligned.m8n8.x4.trans.shared.b16 {%0,%1,%2,%3}, [%4];"
        : "=r"(r[0]), "=r"(r[1]), "=r"(r[2]), "=r"(r[3]) : "r"(addr));
}

// ===========================================================================
// prep_w: convert Wq/Wk/Wv fp32 -> bf16 hi/lo once.  grid (64, 3) x 256
// ===========================================================================
__global__ __launch_bounds__(256)
void prep_w(const float* __restrict__ Wq, const float* __restrict__ Wk,
            const float* __restrict__ Wv)
{
    const int which = blockIdx.y;
    const float* W = (which == 0) ? Wq : (which == 1) ? Wk : Wv;
    const int n = blockIdx.x;
    const int col = threadIdx.x * 4;
    const float4 v = *(const float4*)(W + n * DM_ + col);
    uint32_t h0, l0, h1, l1;
    split2(v.x, v.y, h0, l0);
    split2(v.z, v.w, h1, l1);
    const size_t off = (size_t)which * DK_ * DM_ + n * DM_ + col;
    *(uint2*)(g_wh + off) = make_uint2(h0, h1);
    *(uint2*)(g_wl + off) = make_uint2(l0, l1);
}

// ===========================================================================
// proj_tc: C[8192x64] = A[8192x1024] @ W^T + bias, bf16 hi/lo 3-pass mma.
// CTA: 128 rows (8 warps x 16), K-chunks of 64.  grid (64, 3) x 256.
// smem: A_h 16K | A_l 16K | W_h 8K | W_l 8K  (16B-chunk XOR swizzle)
// ===========================================================================
#define PSM_AH 0
#define PSM_AL 16384
#define PSM_WH 32768
#define PSM_WL 40960
#define PSM_TOTAL 49152

__global__ __launch_bounds__(256)
void proj_tc(const float* __restrict__ Qin, const float* __restrict__ Kin,
             const float* __restrict__ Vin,
             const float* __restrict__ bq, const float* __restrict__ bk,
             const float* __restrict__ bv)
{
    extern __shared__ char ps[];
    const uint32_t a_Ah = smem_to_u32(ps + PSM_AH);
    const uint32_t a_Al = smem_to_u32(ps + PSM_AL);
    const uint32_t a_Wh = smem_to_u32(ps + PSM_WH);
    const uint32_t a_Wl = smem_to_u32(ps + PSM_WL);

    const int which = blockIdx.y;
    const float* A    = (which == 0) ? Qin : (which == 1) ? Kin : Vin;
    const float* bias = (which == 0) ? bq  : (which == 1) ? bk  : bv;
    __nv_bfloat16* H  = (which == 0) ? g_qh : (which == 1) ? g_kh : g_vh;
    __nv_bfloat16* L  = (which == 0) ? g_ql : (which == 1) ? g_kl : g_vl;
    const __nv_bfloat16* Wh = g_wh + (size_t)which * DK_ * DM_;
    const __nv_bfloat16* Wl = g_wl + (size_t)which * DK_ * DM_;

    const int tid  = threadIdx.x;
    const int wid  = tid >> 5;
    const int lane = tid & 31;
    const int m0   = blockIdx.x * 128;

    float c[8][4];
#pragma unroll
    for (int i = 0; i < 8; i++)
#pragma unroll
        for (int j = 0; j < 4; j++) c[i][j] = 0.f;

    // ldmatrix addressing pieces
    const int arow = wid * 16 + ((lane >> 3) & 1) * 8 + (lane & 7);  // A-frag
    const int acsel = lane >> 4;
    const int brow = ((lane >> 4) << 3) + (lane & 7);                 // B-frag (per nt add nt*16)
    const int bcsel = (lane >> 3) & 1;

    for (int kb = 0; kb < DM_; kb += 64) {
        __syncthreads();
        // --- A tile 128x64 fp32 -> bf16 hi/lo, swizzled
#pragma unroll
        for (int idx = tid; idx < 1024; idx += 256) {
            const int r = idx >> 3, g = idx & 7;
            const float* src = A + (size_t)(m0 + r) * DM_ + kb + g * 8;
            const float4 f0 = *(const float4*)src;
            const float4 f1 = *(const float4*)(src + 4);
            uint4 hv, lv;
            split2(f0.x, f0.y, hv.x, lv.x);
            split2(f0.z, f0.w, hv.y, lv.y);
            split2(f1.x, f1.y, hv.z, lv.z);
            split2(f1.z, f1.w, hv.w, lv.w);
            const uint32_t off = (uint32_t)(r * 128 + ((g ^ (r & 7)) * 16));
            *(uint4*)(ps + PSM_AH + off) = hv;
            *(uint4*)(ps + PSM_AL + off) = lv;
        }
        // --- W tile 64x64 bf16 (preconverted), swizzled
#pragma unroll
        for (int idx = tid; idx < 512; idx += 256) {
            const int n = idx >> 3, g = idx & 7;
            const uint32_t off = (uint32_t)(n * 128 + ((g ^ (n & 7)) * 16));
            *(uint4*)(ps + PSM_WH + off) = *(const uint4*)(Wh + (size_t)n * DM_ + kb + g * 8);
            *(uint4*)(ps + PSM_WL + off) = *(const uint4*)(Wl + (size_t)n * DM_ + kb + g * 8);
        }
        __syncthreads();

        // --- A fragments for all 4 k16 chunks
        uint32_t ah[4][4], al[4][4];
#pragma unroll
        for (int kc = 0; kc < 4; kc++) {
            const int ch = kc * 2 + acsel;
            const uint32_t off = (uint32_t)(arow * 128 + ((ch ^ (arow & 7)) * 16));
            ldsm4(ah[kc], a_Ah + off);
            ldsm4(al[kc], a_Al + off);
        }
        // --- B fragments + 3-pass mma
#pragma unroll
        for (int nt = 0; nt < 4; nt++) {
            const int row = nt * 16 + brow;
#pragma unroll
            for (int kc = 0; kc < 4; kc++) {
                const int ch = kc * 2 + bcsel;
                const uint32_t off = (uint32_t)(row * 128 + ((ch ^ (row & 7)) * 16));
                uint32_t wh[4], wl[4];
                ldsm4(wh, a_Wh + off);
                ldsm4(wl, a_Wl + off);
                mma_bf16(c[nt * 2],     ah[kc], wh[0], wh[1]);
                mma_bf16(c[nt * 2],     ah[kc], wl[0], wl[1]);
                mma_bf16(c[nt * 2],     al[kc], wh[0], wh[1]);
                mma_bf16(c[nt * 2 + 1], ah[kc], wh[2], wh[3]);
                mma_bf16(c[nt * 2 + 1], ah[kc], wl[2], wl[3]);
                mma_bf16(c[nt * 2 + 1], al[kc], wh[2], wh[3]);
            }
        }
    }

    // --- epilogue: bias, hi/lo split, row-major store
    const int grp = lane >> 2;
    const int qp  = (lane & 3) * 2;
    const size_t row0 = (size_t)(m0 + wid * 16 + grp);
    const size_t row1 = row0 + 8;
#pragma unroll
    for (int nt = 0; nt < 8; nt++) {
        const int col = nt * 8 + qp;
        const float b0 = bias[col], b1 = bias[col + 1];
        uint32_t h, l;
        split2(c[nt][0] + b0, c[nt][1] + b1, h, l);
        *(uint32_t*)(H + row0 * DK_ + col) = h;
        *(uint32_t*)(L + row0 * DK_ + col) = l;
        split2(c[nt][2] + b0, c[nt][3] + b1, h, l);
        *(uint32_t*)(H + row1 * DK_ + col) = h;
        *(uint32_t*)(L + row1 * DK_ + col) = l;
    }
}

// ===========================================================================
// mma.sync attention: 128-q CTA (8 warps x 16 rows), 64-key tiles, kv-split 2.
// V consumed row-major via ldmatrix.trans.  3-pass bf16 hi/lo on both GEMMs.
// ===========================================================================
__global__ __launch_bounds__(256)
void attn_mma_kernel(const int* __restrict__ mask)
{
    __shared__ __align__(16) __nv_bfloat16 s_kh[64 * 64];
    __shared__ __align__(16) __nv_bfloat16 s_kl[64 * 64];
    __shared__ __align__(16) __nv_bfloat16 s_vh[64 * 64];   // row-major [key][d]
    __shared__ __align__(16) __nv_bfloat16 s_vl[64 * 64];

    const int tid  = threadIdx.x;
    const int wid  = tid >> 5;
    const int lane = tid & 31;
    const int grp  = lane >> 2;
    const int qp   = (lane & 3) * 2;

    const int b     = blockIdx.y;
    const int sp    = blockIdx.z;
    const int q0    = blockIdx.x * 128;
    const int kbase = sp * 2048;
    const int qrow0 = q0 + wid * 16;
    const size_t bS = (size_t)b * S_;

    const uint32_t a_kh = smem_to_u32(s_kh);
    const uint32_t a_kl = smem_to_u32(s_kl);
    const uint32_t a_vh = smem_to_u32(s_vh);
    const uint32_t a_vl = smem_to_u32(s_vl);

    // Q fragments (hi/lo) from global, A-frag m16k16 layout
    uint32_t qh[4][4], ql[4][4];
    {
        const size_t r0 = (bS + qrow0 + grp) * DK_;
        const size_t r1 = r0 + 8 * DK_;
#pragma unroll
        for (int c = 0; c < 4; c++) {
            qh[c][0] = *(const uint32_t*)(g_qh + r0 + c * 16 + qp);
            qh[c][1] = *(const uint32_t*)(g_qh + r1 + c * 16 + qp);
            qh[c][2] = *(const uint32_t*)(g_qh + r0 + c * 16 + qp + 8);
            qh[c][3] = *(const uint32_t*)(g_qh + r1 + c * 16 + qp + 8);
            ql[c][0] = *(const uint32_t*)(g_ql + r0 + c * 16 + qp);
            ql[c][1] = *(const uint32_t*)(g_ql + r1 + c * 16 + qp);
            ql[c][2] = *(const uint32_t*)(g_ql + r0 + c * 16 + qp + 8);
            ql[c][3] = *(const uint32_t*)(g_ql + r1 + c * 16 + qp + 8);
        }
    }

    float O[32];
#pragma unroll
    for (int i = 0; i < 32; i++) O[i] = 0.f;
    float l0 = 0.f, l1 = 0.f;

    // K-tile (non-trans B) addressing
    const int k_rhalf = (lane >> 4) << 3;
    const int k_csel  = (lane >> 3) & 1;
    const int k_i     = lane & 7;
    // V-tile (trans B, row-major) addressing: rows = k, chunks = d
    const int v_rhalf = ((lane >> 3) & 1) << 3;
    const int v_csel  = lane >> 4;

    const size_t mrow0 = (bS + qrow0 + grp) * S_;
    const size_t mrow1 = mrow0 + (size_t)8 * S_;

    for (int t = 0; t < 32; t++) {
        const int k0 = kbase + t * 64;
        __syncthreads();
        {
            const size_t krow = bS + k0;
#pragma unroll
            for (int idx = tid; idx < 512; idx += 256) {
                const int r = idx >> 3, g = idx & 7;
                const uint32_t off = (uint32_t)(r * 128 + ((g ^ (r & 7)) * 16));
                *(uint4*)((char*)s_kh + off) = *(const uint4*)(g_kh + (krow + r) * DK_ + g * 8);
                *(uint4*)((char*)s_kl + off) = *(const uint4*)(g_kl + (krow + r) * DK_ + g * 8);
                *(uint4*)((char*)s_vh + off) = *(const uint4*)(g_vh + (krow + r) * DK_ + g * 8);
                *(uint4*)((char*)s_vl + off) = *(const uint4*)(g_vl + (krow + r) * DK_ + g * 8);
            }
        }
        __syncthreads();

        // ---- scores + softmax + P fragments
        uint32_t ph[4][4], pl[4][4];
#pragma unroll
        for (int nt2 = 0; nt2 < 4; nt2++) {
            float cA[4] = {0.f, 0.f, 0.f, 0.f};
            float cB[4] = {0.f, 0.f, 0.f, 0.f};
#pragma unroll
            for (int c = 0; c < 4; c++) {
                const int row = nt2 * 16 + k_rhalf + k_i;
                const uint32_t off = (uint32_t)(row * 128 + (((c * 2 + k_csel) ^ (row & 7)) * 16));
                uint32_t bh[4], bl[4];
                ldsm4(bh, a_kh + off);
                ldsm4(bl, a_kl + off);
                mma_bf16(cA, qh[c], bh[0], bh[1]);
                mma_bf16(cA, qh[c], bl[0], bl[1]);
                mma_bf16(cA, ql[c], bh[0], bh[1]);
                mma_bf16(cB, qh[c], bh[2], bh[3]);
                mma_bf16(cB, qh[c], bl[2], bl[3]);
                mma_bf16(cB, ql[c], bh[2], bh[3]);
            }
#pragma unroll
            for (int half = 0; half < 2; half++) {
                float* cc = half ? cB : cA;
                const int col = k0 + nt2 * 16 + half * 8 + qp;
                const int2 mA = *(const int2*)(mask + mrow0 + col);
                const int2 mB = *(const int2*)(mask + mrow1 + col);
                const float p0 = mA.x ? __expf(cc[0] * 0.125f) : 0.f;
                const float p1 = mA.y ? __expf(cc[1] * 0.125f) : 0.f;
                const float p2 = mB.x ? __expf(cc[2] * 0.125f) : 0.f;
                const float p3 = mB.y ? __expf(cc[3] * 0.125f) : 0.f;
                l0 += p0 + p1;
                l1 += p2 + p3;
                const __nv_bfloat16 h0 = __float2bfloat16(p0), h1 = __float2bfloat16(p1);
                const __nv_bfloat16 h2 = __float2bfloat16(p2), h3 = __float2bfloat16(p3);
                ph[nt2][half * 2 + 0] = pack_bf16(h0, h1);
                ph[nt2][half * 2 + 1] = pack_bf16(h2, h3);
                pl[nt2][half * 2 + 0] = pack_bf16(__float2bfloat16(p0 - __bfloat162float(h0)),
                                                  __float2bfloat16(p1 - __bfloat162float(h1)));
                pl[nt2][half * 2 + 1] = pack_bf16(__float2bfloat16(p2 - __bfloat162float(h2)),
                                                  __float2bfloat16(p3 - __bfloat162float(h3)));
            }
        }

        // ---- O += P @ V  (row-major V via ldmatrix.trans)
#pragma unroll
        for (int dt2 = 0; dt2 < 4; dt2++) {
            float* oA = &O[dt2 * 8];
            float* oB = &O[dt2 * 8 + 4];
#pragma unroll
            for (int kc = 0; kc < 4; kc++) {
                const int row = kc * 16 + v_rhalf + k_i;
                const uint32_t off = (uint32_t)(row * 128 + (((dt2 * 2 + v_csel) ^ (row & 7)) * 16));
                uint32_t bh[4], bl[4];
                ldsm4t(bh, a_vh + off);
                ldsm4t(bl, a_vl + off);
                mma_bf16(oA, ph[kc], bh[0], bh[1]);
                mma_bf16(oA, ph[kc], bl[0], bl[1]);
                mma_bf16(oA, pl[kc], bh[0], bh[1]);
                mma_bf16(oB, ph[kc], bh[2], bh[3]);
                mma_bf16(oB, ph[kc], bl[2], bl[3]);
                mma_bf16(oB, pl[kc], bh[2], bh[3]);
            }
        }
    }

    // ---- epilogue
    l0 += __shfl_xor_sync(0xffffffffu, l0, 1);
    l0 += __shfl_xor_sync(0xffffffffu, l0, 2);
    l1 += __shfl_xor_sync(0xffffffffu, l1, 1);
    l1 += __shfl_xor_sync(0xffffffffu, l1, 2);
    if ((lane & 3) == 0) {
        g_pl[sp][bS + qrow0 + grp]     = l0;
        g_pl[sp][bS + qrow0 + grp + 8] = l1;
    }
    float* dst0 = g_pacc[sp] + (bS + qrow0 + grp) * DK_;
    float* dst1 = dst0 + 8 * DK_;
#pragma unroll
    for (int dt = 0; dt < 8; dt++) {
        const int col = dt * 8 + qp;
        *(float2*)(dst0 + col) = make_float2(O[dt * 4 + 0], O[dt * 4 + 1]);
        *(float2*)(dst1 + col) = make_float2(O[dt * 4 + 2], O[dt * 4 + 3]);
    }
}

// ===========================================================================
// Merge the 2 kv-splits: y = (acc0 + acc1) / (l0 + l1)
// ===========================================================================
__global__ __launch_bounds__(256)
void merge_kernel(float* __restrict__ out)
{
    const int idx = blockIdx.x * 256 + threadIdx.x;
    const int r = idx >> 6;
    const float l = g_pl[0][r] + g_pl[1][r];
    out[idx] = (g_pacc[0][idx] + g_pacc[1][idx]) / l;
}

// ===========================================================================
extern "C" void kernel_launch(void* const* d_in, const int* in_sizes, int n_in,
                              void* d_out, int out_size)
{
    const float* Q    = (const float*)d_in[0];
    const float* K    = (const float*)d_in[1];
    const float* V    = (const float*)d_in[2];
    const int*   mask = (const int*)  d_in[3];
    const float* Wq   = (const float*)d_in[4];
    const float* bq   = (const float*)d_in[5];
    const float* Wk   = (const float*)d_in[6];
    const float* bk   = (const float*)d_in[7];
    const float* Wv   = (const float*)d_in[8];
    const float* bv   = (const float*)d_in[9];
    float* out = (float*)d_out;

    prep_w<<<dim3(DK_, 3), 256>>>(Wq, Wk, Wv);

    cudaFuncSetAttribute(proj_tc, cudaFuncAttributeMaxDynamicSharedMemorySize, PSM_TOTAL);
    proj_tc<<<dim3((B_ * S_) / 128, 3), 256, PSM_TOTAL>>>(Q, K, V, bq, bk, bv);

    attn_mma_kernel<<<dim3(S_ / 128, B_, 2), 256>>>(mask);

    merge_kernel<<<(B_ * S_ * DK_) / 256, 256>>>(out);
}

// round 6
// speedup vs baseline: 4.8437x; 1.4047x over previous
#include <cuda_runtime.h>
#include <cuda_bf16.h>
#include <cstdint>

#define B_   2
#define S_   4096
#define DM_  1024
#define DK_  64

// ===========================================================================
// Scratch (__device__ globals per allocation rules)
// ===========================================================================
__device__ __nv_bfloat16 g_qh[B_ * S_ * DK_];
__device__ __nv_bfloat16 g_ql[B_ * S_ * DK_];
__device__ __nv_bfloat16 g_kh[B_ * S_ * DK_];
__device__ __nv_bfloat16 g_kl[B_ * S_ * DK_];
__device__ __nv_bfloat16 g_vh[B_ * S_ * DK_];    // row-major [b][s][d]
__device__ __nv_bfloat16 g_vl[B_ * S_ * DK_];
__device__ __nv_bfloat16 g_wh[3 * DK_ * DM_];    // pre-converted W hi/lo
__device__ __nv_bfloat16 g_wl[3 * DK_ * DM_];
__device__ float g_pacc[2][B_ * S_ * DK_];       // per-split unnormalized O
__device__ float g_pl[2][B_ * S_];               // per-split softmax denominators

__device__ __forceinline__ uint32_t smem_to_u32(const void* p) {
    uint32_t a;
    asm("{ .reg .u64 t; cvta.to.shared.u64 t, %1; cvt.u32.u64 %0, t; }" : "=r"(a) : "l"(p));
    return a;
}
__device__ __forceinline__ uint32_t pack_bf16(__nv_bfloat16 a, __nv_bfloat16 b) {
    return (uint32_t)__bfloat16_as_ushort(a) | ((uint32_t)__bfloat16_as_ushort(b) << 16);
}
__device__ __forceinline__ void split2(float a, float b, uint32_t& h, uint32_t& l) {
    const __nv_bfloat16 ha = __float2bfloat16(a);
    const __nv_bfloat16 hb = __float2bfloat16(b);
    h = pack_bf16(ha, hb);
    l = pack_bf16(__float2bfloat16(a - __bfloat162float(ha)),
                  __float2bfloat16(b - __bfloat162float(hb)));
}
__device__ __forceinline__ void mma_bf16(float c[4], const uint32_t a[4],
                                         uint32_t b0, uint32_t b1) {
    asm volatile("mma.sync.aligned.m16n8k16.row.col.f32.bf16.bf16.f32 "
        "{%0,%1,%2,%3}, {%4,%5,%6,%7}, {%8,%9}, {%0,%1,%2,%3};"
        : "+f"(c[0]), "+f"(c[1]), "+f"(c[2]), "+f"(c[3])
        : "r"(a[0]), "r"(a[1]), "r"(a[2]), "r"(a[3]), "r"(b0), "r"(b1));
}
__device__ __forceinline__ void ldsm4(uint32_t r[4], uint32_t addr) {
    asm volatile("ldmatrix.sync.aligned.m8n8.x4.shared.b16 {%0,%1,%2,%3}, [%4];"
        : "=r"(r[0]), "=r"(r[1]), "=r"(r[2]), "=r"(r[3]) : "r"(addr));
}
__device__ __forceinline__ void ldsm4t(uint32_t r[4], uint32_t addr) {
    asm volatile("ldmatrix.sync.aligned.m8n8.x4.trans.shared.b16 {%0,%1,%2,%3}, [%4];"
        : "=r"(r[0]), "=r"(r[1]), "=r"(r[2]), "=r"(r[3]) : "r"(addr));
}
__device__ __forceinline__ void cp16(uint32_t smem, const void* g) {
    asm volatile("cp.async.cg.shared.global [%0], [%1], 16;" :: "r"(smem), "l"(g));
}
__device__ __forceinline__ void cp_commit() {
    asm volatile("cp.async.commit_group;");
}
template <int N>
__device__ __forceinline__ void cp_wait() {
    asm volatile("cp.async.wait_group %0;" :: "n"(N));
}

// ===========================================================================
// prep_w: convert Wq/Wk/Wv fp32 -> bf16 hi/lo once.  grid (64, 3) x 256
// ===========================================================================
__global__ __launch_bounds__(256)
void prep_w(const float* __restrict__ Wq, const float* __restrict__ Wk,
            const float* __restrict__ Wv)
{
    const int which = blockIdx.y;
    const float* W = (which == 0) ? Wq : (which == 1) ? Wk : Wv;
    const int n = blockIdx.x;
    const int col = threadIdx.x * 4;
    const float4 v = *(const float4*)(W + n * DM_ + col);
    uint32_t h0, l0, h1, l1;
    split2(v.x, v.y, h0, l0);
    split2(v.z, v.w, h1, l1);
    const size_t off = (size_t)which * DK_ * DM_ + n * DM_ + col;
    *(uint2*)(g_wh + off) = make_uint2(h0, h1);
    *(uint2*)(g_wl + off) = make_uint2(l0, l1);
}

// ===========================================================================
// proj_tc: C[8192x64] = A @ W^T + bias, bf16 hi/lo 3-pass mma, pipelined.
// CTA: 64 rows (4 warps x 16), K-chunks of 64.  grid (128, 3) x 128.
// A chunk prefetched in registers; W chunks double-buffered via cp.async.
// smem: A_h 8K | A_l 8K | W[2] 16K each = 48K
// ===========================================================================
#define PSM_AH 0
#define PSM_AL 8192
#define PSM_W  16384          /* + stage*16384 ; WH +0, WL +8192 */
#define PSM_TOTAL 49152

__global__ __launch_bounds__(128)
void proj_tc(const float* __restrict__ Qin, const float* __restrict__ Kin,
             const float* __restrict__ Vin,
             const float* __restrict__ bq, const float* __restrict__ bk,
             const float* __restrict__ bv)
{
    extern __shared__ char ps[];
    const uint32_t sb = smem_to_u32(ps);

    const int which = blockIdx.y;
    const float* A    = (which == 0) ? Qin : (which == 1) ? Kin : Vin;
    const float* bias = (which == 0) ? bq  : (which == 1) ? bk  : bv;
    __nv_bfloat16* H  = (which == 0) ? g_qh : (which == 1) ? g_kh : g_vh;
    __nv_bfloat16* L  = (which == 0) ? g_ql : (which == 1) ? g_kl : g_vl;
    const __nv_bfloat16* Wh = g_wh + (size_t)which * DK_ * DM_;
    const __nv_bfloat16* Wl = g_wl + (size_t)which * DK_ * DM_;

    const int tid  = threadIdx.x;
    const int wid  = tid >> 5;
    const int lane = tid & 31;
    const int m0   = blockIdx.x * 64;

    float c[8][4];
#pragma unroll
    for (int i = 0; i < 8; i++)
#pragma unroll
        for (int j = 0; j < 4; j++) c[i][j] = 0.f;

    const int arow  = wid * 16 + ((lane >> 3) & 1) * 8 + (lane & 7);
    const int acsel = lane >> 4;
    const int brow  = ((lane >> 4) << 3) + (lane & 7);
    const int bcsel = (lane >> 3) & 1;

    // per-thread A-chunk positions (4 of them)
    const int pr[4] = { (tid + 0)   >> 3, (tid + 128) >> 3,
                        (tid + 256) >> 3, (tid + 384) >> 3 };
    const int pg    = tid & 7;

    // W fill for chunk kc into stage st
    auto fillW = [&](int kc, int st) {
        const uint32_t wb = sb + PSM_W + st * 16384;
#pragma unroll
        for (int idx = tid; idx < 512; idx += 128) {
            const int n = idx >> 3, g = idx & 7;
            const uint32_t off = (uint32_t)(n * 128 + ((g ^ (n & 7)) * 16));
            cp16(wb + off,        Wh + (size_t)n * DM_ + kc * 64 + g * 8);
            cp16(wb + 8192 + off, Wl + (size_t)n * DM_ + kc * 64 + g * 8);
        }
        cp_commit();
    };

    float4 aPre[8];
#pragma unroll
    for (int i = 0; i < 4; i++) {
        const float* src = A + (size_t)(m0 + pr[i]) * DM_ + pg * 8;
        aPre[2 * i]     = *(const float4*)src;
        aPre[2 * i + 1] = *(const float4*)(src + 4);
    }
    fillW(0, 0);

    for (int kc = 0; kc < 16; kc++) {
        cp_wait<0>();
        __syncthreads();
        // store A bf16 hi/lo (from prefetched regs)
#pragma unroll
        for (int i = 0; i < 4; i++) {
            uint4 hv, lv;
            split2(aPre[2 * i].x,     aPre[2 * i].y,     hv.x, lv.x);
            split2(aPre[2 * i].z,     aPre[2 * i].w,     hv.y, lv.y);
            split2(aPre[2 * i + 1].x, aPre[2 * i + 1].y, hv.z, lv.z);
            split2(aPre[2 * i + 1].z, aPre[2 * i + 1].w, hv.w, lv.w);
            const uint32_t off = (uint32_t)(pr[i] * 128 + ((pg ^ (pr[i] & 7)) * 16));
            *(uint4*)(ps + PSM_AH + off) = hv;
            *(uint4*)(ps + PSM_AL + off) = lv;
        }
        if (kc < 15) {
#pragma unroll
            for (int i = 0; i < 4; i++) {
                const float* src = A + (size_t)(m0 + pr[i]) * DM_ + (kc + 1) * 64 + pg * 8;
                aPre[2 * i]     = *(const float4*)src;
                aPre[2 * i + 1] = *(const float4*)(src + 4);
            }
            fillW(kc + 1, (kc + 1) & 1);
        }
        __syncthreads();

        const uint32_t a_Ah = sb + PSM_AH;
        const uint32_t a_Al = sb + PSM_AL;
        const uint32_t a_Wh = sb + PSM_W + (kc & 1) * 16384;
        const uint32_t a_Wl = a_Wh + 8192;

        uint32_t ah[4][4], al[4][4];
#pragma unroll
        for (int k4 = 0; k4 < 4; k4++) {
            const int ch = k4 * 2 + acsel;
            const uint32_t off = (uint32_t)(arow * 128 + ((ch ^ (arow & 7)) * 16));
            ldsm4(ah[k4], a_Ah + off);
            ldsm4(al[k4], a_Al + off);
        }
#pragma unroll
        for (int nt = 0; nt < 4; nt++) {
            const int row = nt * 16 + brow;
#pragma unroll
            for (int k4 = 0; k4 < 4; k4++) {
                const int ch = k4 * 2 + bcsel;
                const uint32_t off = (uint32_t)(row * 128 + ((ch ^ (row & 7)) * 16));
                uint32_t wh[4], wl[4];
                ldsm4(wh, a_Wh + off);
                ldsm4(wl, a_Wl + off);
                mma_bf16(c[nt * 2],     ah[k4], wh[0], wh[1]);
                mma_bf16(c[nt * 2],     ah[k4], wl[0], wl[1]);
                mma_bf16(c[nt * 2],     al[k4], wh[0], wh[1]);
                mma_bf16(c[nt * 2 + 1], ah[k4], wh[2], wh[3]);
                mma_bf16(c[nt * 2 + 1], ah[k4], wl[2], wl[3]);
                mma_bf16(c[nt * 2 + 1], al[k4], wh[2], wh[3]);
            }
        }
    }

    // epilogue: bias, hi/lo split, row-major store
    const int grp = lane >> 2;
    const int qp  = (lane & 3) * 2;
    const size_t row0 = (size_t)(m0 + wid * 16 + grp);
    const size_t row1 = row0 + 8;
#pragma unroll
    for (int nt = 0; nt < 8; nt++) {
        const int col = nt * 8 + qp;
        const float b0 = bias[col], b1 = bias[col + 1];
        uint32_t h, l;
        split2(c[nt][0] + b0, c[nt][1] + b1, h, l);
        *(uint32_t*)(H + row0 * DK_ + col) = h;
        *(uint32_t*)(L + row0 * DK_ + col) = l;
        split2(c[nt][2] + b0, c[nt][3] + b1, h, l);
        *(uint32_t*)(H + row1 * DK_ + col) = h;
        *(uint32_t*)(L + row1 * DK_ + col) = l;
    }
}

// ===========================================================================
// attention: 64-q CTA (4 warps x 16 rows), 64-key tiles, kv-split 2.
// cp.async double-buffered K/V hi/lo + mask tiles. grid (64, 2, 2) x 128.
// smem: KV[2]: 32K each (KH,KL,VH,VL 8K) | mask[2]: 17408 each (stride 272B)
// ===========================================================================
#define ASM_KV    0            /* + stage*32768 */
#define ASM_MASK  65536        /* + stage*17408 */
#define ASM_TOTAL 100352

__global__ __launch_bounds__(128)
void attn_mma_kernel(const int* __restrict__ mask)
{
    extern __shared__ char sm[];
    const uint32_t sb = smem_to_u32(sm);

    const int tid  = threadIdx.x;
    const int wid  = tid >> 5;
    const int lane = tid & 31;
    const int grp  = lane >> 2;
    const int qp   = (lane & 3) * 2;

    const int b     = blockIdx.y;
    const int sp    = blockIdx.z;
    const int q0    = blockIdx.x * 64;
    const int kbase = sp * 2048;
    const int qrow0 = q0 + wid * 16;
    const size_t bS = (size_t)b * S_;

    // Q fragments (hi/lo) from global, A-frag m16k16 layout
    uint32_t qh[4][4], ql[4][4];
    {
        const size_t r0 = (bS + qrow0 + grp) * DK_;
        const size_t r1 = r0 + 8 * DK_;
#pragma unroll
        for (int c = 0; c < 4; c++) {
            qh[c][0] = *(const uint32_t*)(g_qh + r0 + c * 16 + qp);
            qh[c][1] = *(const uint32_t*)(g_qh + r1 + c * 16 + qp);
            qh[c][2] = *(const uint32_t*)(g_qh + r0 + c * 16 + qp + 8);
            qh[c][3] = *(const uint32_t*)(g_qh + r1 + c * 16 + qp + 8);
            ql[c][0] = *(const uint32_t*)(g_ql + r0 + c * 16 + qp);
            ql[c][1] = *(const uint32_t*)(g_ql + r1 + c * 16 + qp);
            ql[c][2] = *(const uint32_t*)(g_ql + r0 + c * 16 + qp + 8);
            ql[c][3] = *(const uint32_t*)(g_ql + r1 + c * 16 + qp + 8);
        }
    }

    float O[32];
#pragma unroll
    for (int i = 0; i < 32; i++) O[i] = 0.f;
    float l0 = 0.f, l1 = 0.f;

    const int k_rhalf = (lane >> 4) << 3;
    const int k_csel  = (lane >> 3) & 1;
    const int k_i     = lane & 7;
    const int v_rhalf = ((lane >> 3) & 1) << 3;
    const int v_csel  = lane >> 4;

    // async fill of tile tt into stage tt&1 (K/V hi/lo + mask)
    auto fill = [&](int tt) {
        const int st = tt & 1;
        const uint32_t kvb = sb + ASM_KV + st * 32768;
        const int kk0 = kbase + tt * 64;
        const size_t krow = bS + kk0;
#pragma unroll
        for (int idx = tid; idx < 512; idx += 128) {
            const int r = idx >> 3, g = idx & 7;
            const uint32_t off = (uint32_t)(r * 128 + ((g ^ (r & 7)) * 16));
            const size_t so = (krow + r) * DK_ + g * 8;
            cp16(kvb + off,         g_kh + so);
            cp16(kvb + 8192 + off,  g_kl + so);
            cp16(kvb + 16384 + off, g_vh + so);
            cp16(kvb + 24576 + off, g_vl + so);
        }
        const uint32_t mb = sb + ASM_MASK + st * 17408;
#pragma unroll
        for (int idx = tid; idx < 1024; idx += 128) {
            const int r = idx >> 4, c = idx & 15;
            cp16(mb + r * 272 + c * 16, mask + (bS + q0 + r) * S_ + kk0 + c * 4);
        }
        cp_commit();
    };

    fill(0);

    for (int t = 0; t < 32; t++) {
        cp_wait<0>();
        __syncthreads();
        if (t + 1 < 32) fill(t + 1);

        const int st = t & 1;
        const uint32_t a_kh = sb + ASM_KV + st * 32768;
        const uint32_t a_kl = a_kh + 8192;
        const uint32_t a_vh = a_kh + 16384;
        const uint32_t a_vl = a_kh + 24576;
        const char* mptr = sm + ASM_MASK + st * 17408;

        // ---- scores + softmax + P fragments
        uint32_t ph[4][4], pl[4][4];
#pragma unroll
        for (int nt2 = 0; nt2 < 4; nt2++) {
            float cA[4] = {0.f, 0.f, 0.f, 0.f};
            float cB[4] = {0.f, 0.f, 0.f, 0.f};
#pragma unroll
            for (int c = 0; c < 4; c++) {
                const int row = nt2 * 16 + k_rhalf + k_i;
                const uint32_t off = (uint32_t)(row * 128 + (((c * 2 + k_csel) ^ (row & 7)) * 16));
                uint32_t bh[4], bl[4];
                ldsm4(bh, a_kh + off);
                ldsm4(bl, a_kl + off);
                mma_bf16(cA, qh[c], bh[0], bh[1]);
                mma_bf16(cA, qh[c], bl[0], bl[1]);
                mma_bf16(cA, ql[c], bh[0], bh[1]);
                mma_bf16(cB, qh[c], bh[2], bh[3]);
                mma_bf16(cB, qh[c], bl[2], bl[3]);
                mma_bf16(cB, ql[c], bh[2], bh[3]);
            }
#pragma unroll
            for (int half = 0; half < 2; half++) {
                float* cc = half ? cB : cA;
                const int colw = nt2 * 16 + half * 8 + qp;
                const int2 mA = *(const int2*)(mptr + (wid * 16 + grp) * 272 + colw * 4);
                const int2 mB = *(const int2*)(mptr + (wid * 16 + grp + 8) * 272 + colw * 4);
                const float p0 = mA.x ? __expf(cc[0] * 0.125f) : 0.f;
                const float p1 = mA.y ? __expf(cc[1] * 0.125f) : 0.f;
                const float p2 = mB.x ? __expf(cc[2] * 0.125f) : 0.f;
                const float p3 = mB.y ? __expf(cc[3] * 0.125f) : 0.f;
                l0 += p0 + p1;
                l1 += p2 + p3;
                const __nv_bfloat16 h0 = __float2bfloat16(p0), h1 = __float2bfloat16(p1);
                const __nv_bfloat16 h2 = __float2bfloat16(p2), h3 = __float2bfloat16(p3);
                ph[nt2][half * 2 + 0] = pack_bf16(h0, h1);
                ph[nt2][half * 2 + 1] = pack_bf16(h2, h3);
                pl[nt2][half * 2 + 0] = pack_bf16(__float2bfloat16(p0 - __bfloat162float(h0)),
                                                  __float2bfloat16(p1 - __bfloat162float(h1)));
                pl[nt2][half * 2 + 1] = pack_bf16(__float2bfloat16(p2 - __bfloat162float(h2)),
                                                  __float2bfloat16(p3 - __bfloat162float(h3)));
            }
        }

        // ---- O += P @ V  (row-major V via ldmatrix.trans)
#pragma unroll
        for (int dt2 = 0; dt2 < 4; dt2++) {
            float* oA = &O[dt2 * 8];
            float* oB = &O[dt2 * 8 + 4];
#pragma unroll
            for (int kc = 0; kc < 4; kc++) {
                const int row = kc * 16 + v_rhalf + k_i;
                const uint32_t off = (uint32_t)(row * 128 + (((dt2 * 2 + v_csel) ^ (row & 7)) * 16));
                uint32_t bh[4], bl[4];
                ldsm4t(bh, a_vh + off);
                ldsm4t(bl, a_vl + off);
                mma_bf16(oA, ph[kc], bh[0], bh[1]);
                mma_bf16(oA, ph[kc], bl[0], bl[1]);
                mma_bf16(oA, pl[kc], bh[0], bh[1]);
                mma_bf16(oB, ph[kc], bh[2], bh[3]);
                mma_bf16(oB, ph[kc], bl[2], bl[3]);
                mma_bf16(oB, pl[kc], bh[2], bh[3]);
            }
        }
        __syncthreads();   // all warps done with stage st before it is refilled
    }

    // ---- epilogue
    l0 += __shfl_xor_sync(0xffffffffu, l0, 1);
    l0 += __shfl_xor_sync(0xffffffffu, l0, 2);
    l1 += __shfl_xor_sync(0xffffffffu, l1, 1);
    l1 += __shfl_xor_sync(0xffffffffu, l1, 2);
    if ((lane & 3) == 0) {
        g_pl[sp][bS + qrow0 + grp]     = l0;
        g_pl[sp][bS + qrow0 + grp + 8] = l1;
    }
    float* dst0 = g_pacc[sp] + (bS + qrow0 + grp) * DK_;
    float* dst1 = dst0 + 8 * DK_;
#pragma unroll
    for (int dt = 0; dt < 8; dt++) {
        const int col = dt * 8 + qp;
        *(float2*)(dst0 + col) = make_float2(O[dt * 4 + 0], O[dt * 4 + 1]);
        *(float2*)(dst1 + col) = make_float2(O[dt * 4 + 2], O[dt * 4 + 3]);
    }
}

// ===========================================================================
// Merge the 2 kv-splits: y = (acc0 + acc1) / (l0 + l1)
// ===========================================================================
__global__ __launch_bounds__(256)
void merge_kernel(float* __restrict__ out)
{
    const int idx = blockIdx.x * 256 + threadIdx.x;
    const int r = idx >> 6;
    const float l = g_pl[0][r] + g_pl[1][r];
    out[idx] = (g_pacc[0][idx] + g_pacc[1][idx]) / l;
}

// ===========================================================================
extern "C" void kernel_launch(void* const* d_in, const int* in_sizes, int n_in,
                              void* d_out, int out_size)
{
    const float* Q    = (const float*)d_in[0];
    const float* K    = (const float*)d_in[1];
    const float* V    = (const float*)d_in[2];
    const int*   mask = (const int*)  d_in[3];
    const float* Wq   = (const float*)d_in[4];
    const float* bq   = (const float*)d_in[5];
    const float* Wk   = (const float*)d_in[6];
    const float* bk   = (const float*)d_in[7];
    const float* Wv   = (const float*)d_in[8];
    const float* bv   = (const float*)d_in[9];
    float* out = (float*)d_out;

    prep_w<<<dim3(DK_, 3), 256>>>(Wq, Wk, Wv);

    cudaFuncSetAttribute(proj_tc, cudaFuncAttributeMaxDynamicSharedMemorySize, PSM_TOTAL);
    proj_tc<<<dim3((B_ * S_) / 64, 3), 128, PSM_TOTAL>>>(Q, K, V, bq, bk, bv);

    cudaFuncSetAttribute(attn_mma_kernel,
                         cudaFuncAttributeMaxDynamicSharedMemorySize, ASM_TOTAL);
    attn_mma_kernel<<<dim3(S_ / 64, B_, 2), 128, ASM_TOTAL>>>(mask);

    merge_kernel<<<(B_ * S_ * DK_) / 256, 256>>>(out);
}

// round 8
// speedup vs baseline: 5.9126x; 1.2207x over previous
#include <cuda_runtime.h>
#include <cuda_bf16.h>
#include <cuda_fp16.h>
#include <cstdint>

#define B_   2
#define S_   4096
#define DM_  1024
#define DK_  64

// ===========================================================================
// Scratch (__device__ globals per allocation rules)
// ===========================================================================
__device__ __half g_qh[B_ * S_ * DK_];           // q fp16 hi
__device__ __half g_ql[B_ * S_ * DK_];           // q fp16 residual
__device__ __half g_k [B_ * S_ * DK_];           // k single fp16
__device__ __half g_v [B_ * S_ * DK_];           // v single fp16 (row-major)
__device__ __nv_bfloat16 g_wh[3 * DK_ * DM_];    // W bf16 hi/lo (proj stays 3-pass)
__device__ __nv_bfloat16 g_wl[3 * DK_ * DM_];
__device__ float g_pacc[2][B_ * S_ * DK_];       // per-split unnormalized O
__device__ float g_pl[2][B_ * S_];               // per-split softmax denominators

__device__ __forceinline__ uint32_t smem_to_u32(const void* p) {
    uint32_t a;
    asm("{ .reg .u64 t; cvta.to.shared.u64 t, %1; cvt.u32.u64 %0, t; }" : "=r"(a) : "l"(p));
    return a;
}
__device__ __forceinline__ uint32_t pack_bf16(__nv_bfloat16 a, __nv_bfloat16 b) {
    return (uint32_t)__bfloat16_as_ushort(a) | ((uint32_t)__bfloat16_as_ushort(b) << 16);
}
__device__ __forceinline__ void split2(float a, float b, uint32_t& h, uint32_t& l) {
    const __nv_bfloat16 ha = __float2bfloat16(a);
    const __nv_bfloat16 hb = __float2bfloat16(b);
    h = pack_bf16(ha, hb);
    l = pack_bf16(__float2bfloat16(a - __bfloat162float(ha)),
                  __float2bfloat16(b - __bfloat162float(hb)));
}
__device__ __forceinline__ uint32_t pack_h2(__half a, __half b) {
    const __half2 v = __halves2half2(a, b);   // a -> low
    return *(const uint32_t*)&v;
}
__device__ __forceinline__ void split2h(float a, float b, uint32_t& h, uint32_t& l) {
    const __half ha = __float2half_rn(a);
    const __half hb = __float2half_rn(b);
    h = pack_h2(ha, hb);
    l = pack_h2(__float2half_rn(a - __half2float(ha)),
                __float2half_rn(b - __half2float(hb)));
}
__device__ __forceinline__ void mma_bf16(float c[4], const uint32_t a[4],
                                         uint32_t b0, uint32_t b1) {
    asm volatile("mma.sync.aligned.m16n8k16.row.col.f32.bf16.bf16.f32 "
        "{%0,%1,%2,%3}, {%4,%5,%6,%7}, {%8,%9}, {%0,%1,%2,%3};"
        : "+f"(c[0]), "+f"(c[1]), "+f"(c[2]), "+f"(c[3])
        : "r"(a[0]), "r"(a[1]), "r"(a[2]), "r"(a[3]), "r"(b0), "r"(b1));
}
__device__ __forceinline__ void mma_f16(float c[4], const uint32_t a[4],
                                        uint32_t b0, uint32_t b1) {
    asm volatile("mma.sync.aligned.m16n8k16.row.col.f32.f16.f16.f32 "
        "{%0,%1,%2,%3}, {%4,%5,%6,%7}, {%8,%9}, {%0,%1,%2,%3};"
        : "+f"(c[0]), "+f"(c[1]), "+f"(c[2]), "+f"(c[3])
        : "r"(a[0]), "r"(a[1]), "r"(a[2]), "r"(a[3]), "r"(b0), "r"(b1));
}
__device__ __forceinline__ void ldsm4(uint32_t r[4], uint32_t addr) {
    asm volatile("ldmatrix.sync.aligned.m8n8.x4.shared.b16 {%0,%1,%2,%3}, [%4];"
        : "=r"(r[0]), "=r"(r[1]), "=r"(r[2]), "=r"(r[3]) : "r"(addr));
}
__device__ __forceinline__ void ldsm4t(uint32_t r[4], uint32_t addr) {
    asm volatile("ldmatrix.sync.aligned.m8n8.x4.trans.shared.b16 {%0,%1,%2,%3}, [%4];"
        : "=r"(r[0]), "=r"(r[1]), "=r"(r[2]), "=r"(r[3]) : "r"(addr));
}
__device__ __forceinline__ void cp16(uint32_t smem, const void* g) {
    asm volatile("cp.async.cg.shared.global [%0], [%1], 16;" :: "r"(smem), "l"(g));
}
__device__ __forceinline__ void cp_commit() {
    asm volatile("cp.async.commit_group;");
}
template <int N>
__device__ __forceinline__ void cp_wait() {
    asm volatile("cp.async.wait_group %0;" :: "n"(N));
}

// ===========================================================================
// prep_w: convert Wq/Wk/Wv fp32 -> bf16 hi/lo once.  grid (64, 3) x 256
// ===========================================================================
__global__ __launch_bounds__(256)
void prep_w(const float* __restrict__ Wq, const float* __restrict__ Wk,
            const float* __restrict__ Wv)
{
    const int which = blockIdx.y;
    const float* W = (which == 0) ? Wq : (which == 1) ? Wk : Wv;
    const int n = blockIdx.x;
    const int col = threadIdx.x * 4;
    const float4 v = *(const float4*)(W + n * DM_ + col);
    uint32_t h0, l0, h1, l1;
    split2(v.x, v.y, h0, l0);
    split2(v.z, v.w, h1, l1);
    const size_t off = (size_t)which * DK_ * DM_ + n * DM_ + col;
    *(uint2*)(g_wh + off) = make_uint2(h0, h1);
    *(uint2*)(g_wl + off) = make_uint2(l0, l1);
}

// ===========================================================================
// proj_tc: C[8192x64] = A @ W^T + bias, bf16 hi/lo 3-pass mma, pipelined.
// Epilogue: which==0 -> q fp16 hi/lo; which==1/2 -> k/v single fp16.
// CTA: 64 rows (4 warps x 16), K-chunks of 64.  grid (128, 3) x 128.
// ===========================================================================
#define PSM_AH 0
#define PSM_AL 8192
#define PSM_W  16384          /* + stage*16384 ; WH +0, WL +8192 */
#define PSM_TOTAL 49152

__global__ __launch_bounds__(128)
void proj_tc(const float* __restrict__ Qin, const float* __restrict__ Kin,
             const float* __restrict__ Vin,
             const float* __restrict__ bq, const float* __restrict__ bk,
             const float* __restrict__ bv)
{
    extern __shared__ char ps[];
    const uint32_t sb = smem_to_u32(ps);

    const int which = blockIdx.y;
    const float* A    = (which == 0) ? Qin : (which == 1) ? Kin : Vin;
    const float* bias = (which == 0) ? bq  : (which == 1) ? bk  : bv;
    const __nv_bfloat16* Wh = g_wh + (size_t)which * DK_ * DM_;
    const __nv_bfloat16* Wl = g_wl + (size_t)which * DK_ * DM_;

    const int tid  = threadIdx.x;
    const int wid  = tid >> 5;
    const int lane = tid & 31;
    const int m0   = blockIdx.x * 64;

    float c[8][4];
#pragma unroll
    for (int i = 0; i < 8; i++)
#pragma unroll
        for (int j = 0; j < 4; j++) c[i][j] = 0.f;

    const int arow  = wid * 16 + ((lane >> 3) & 1) * 8 + (lane & 7);
    const int acsel = lane >> 4;
    const int brow  = ((lane >> 4) << 3) + (lane & 7);
    const int bcsel = (lane >> 3) & 1;

    const int pr[4] = { (tid + 0)   >> 3, (tid + 128) >> 3,
                        (tid + 256) >> 3, (tid + 384) >> 3 };
    const int pg    = tid & 7;

    auto fillW = [&](int kc, int st) {
        const uint32_t wb = sb + PSM_W + st * 16384;
#pragma unroll
        for (int idx = tid; idx < 512; idx += 128) {
            const int n = idx >> 3, g = idx & 7;
            const uint32_t off = (uint32_t)(n * 128 + ((g ^ (n & 7)) * 16));
            cp16(wb + off,        Wh + (size_t)n * DM_ + kc * 64 + g * 8);
            cp16(wb + 8192 + off, Wl + (size_t)n * DM_ + kc * 64 + g * 8);
        }
        cp_commit();
    };

    float4 aPre[8];
#pragma unroll
    for (int i = 0; i < 4; i++) {
        const float* src = A + (size_t)(m0 + pr[i]) * DM_ + pg * 8;
        aPre[2 * i]     = *(const float4*)src;
        aPre[2 * i + 1] = *(const float4*)(src + 4);
    }
    fillW(0, 0);

    for (int kc = 0; kc < 16; kc++) {
        cp_wait<0>();
        __syncthreads();
#pragma unroll
        for (int i = 0; i < 4; i++) {
            uint4 hv, lv;
            split2(aPre[2 * i].x,     aPre[2 * i].y,     hv.x, lv.x);
            split2(aPre[2 * i].z,     aPre[2 * i].w,     hv.y, lv.y);
            split2(aPre[2 * i + 1].x, aPre[2 * i + 1].y, hv.z, lv.z);
            split2(aPre[2 * i + 1].z, aPre[2 * i + 1].w, hv.w, lv.w);
            const uint32_t off = (uint32_t)(pr[i] * 128 + ((pg ^ (pr[i] & 7)) * 16));
            *(uint4*)(ps + PSM_AH + off) = hv;
            *(uint4*)(ps + PSM_AL + off) = lv;
        }
        if (kc < 15) {
#pragma unroll
            for (int i = 0; i < 4; i++) {
                const float* src = A + (size_t)(m0 + pr[i]) * DM_ + (kc + 1) * 64 + pg * 8;
                aPre[2 * i]     = *(const float4*)src;
                aPre[2 * i + 1] = *(const float4*)(src + 4);
            }
            fillW(kc + 1, (kc + 1) & 1);
        }
        __syncthreads();

        const uint32_t a_Ah = sb + PSM_AH;
        const uint32_t a_Al = sb + PSM_AL;
        const uint32_t a_Wh = sb + PSM_W + (kc & 1) * 16384;
        const uint32_t a_Wl = a_Wh + 8192;

        uint32_t ah[4][4], al[4][4];
#pragma unroll
        for (int k4 = 0; k4 < 4; k4++) {
            const int ch = k4 * 2 + acsel;
            const uint32_t off = (uint32_t)(arow * 128 + ((ch ^ (arow & 7)) * 16));
            ldsm4(ah[k4], a_Ah + off);
            ldsm4(al[k4], a_Al + off);
        }
#pragma unroll
        for (int nt = 0; nt < 4; nt++) {
            const int row = nt * 16 + brow;
#pragma unroll
            for (int k4 = 0; k4 < 4; k4++) {
                const int ch = k4 * 2 + bcsel;
                const uint32_t off = (uint32_t)(row * 128 + ((ch ^ (row & 7)) * 16));
                uint32_t wh[4], wl[4];
                ldsm4(wh, a_Wh + off);
                ldsm4(wl, a_Wl + off);
                mma_bf16(c[nt * 2],     ah[k4], wh[0], wh[1]);
                mma_bf16(c[nt * 2],     ah[k4], wl[0], wl[1]);
                mma_bf16(c[nt * 2],     al[k4], wh[0], wh[1]);
                mma_bf16(c[nt * 2 + 1], ah[k4], wh[2], wh[3]);
                mma_bf16(c[nt * 2 + 1], ah[k4], wl[2], wl[3]);
                mma_bf16(c[nt * 2 + 1], al[k4], wh[2], wh[3]);
            }
        }
    }

    // epilogue: bias + fp16 emit
    const int grp = lane >> 2;
    const int qp  = (lane & 3) * 2;
    const size_t row0 = (size_t)(m0 + wid * 16 + grp);
    const size_t row1 = row0 + 8;
    if (which == 0) {
#pragma unroll
        for (int nt = 0; nt < 8; nt++) {
            const int col = nt * 8 + qp;
            const float b0 = bias[col], b1 = bias[col + 1];
            uint32_t h, l;
            split2h(c[nt][0] + b0, c[nt][1] + b1, h, l);
            *(uint32_t*)(g_qh + row0 * DK_ + col) = h;
            *(uint32_t*)(g_ql + row0 * DK_ + col) = l;
            split2h(c[nt][2] + b0, c[nt][3] + b1, h, l);
            *(uint32_t*)(g_qh + row1 * DK_ + col) = h;
            *(uint32_t*)(g_ql + row1 * DK_ + col) = l;
        }
    } else {
        __half* D = (which == 1) ? g_k : g_v;
#pragma unroll
        for (int nt = 0; nt < 8; nt++) {
            const int col = nt * 8 + qp;
            const float b0 = bias[col], b1 = bias[col + 1];
            *(uint32_t*)(D + row0 * DK_ + col) =
                pack_h2(__float2half_rn(c[nt][0] + b0), __float2half_rn(c[nt][1] + b1));
            *(uint32_t*)(D + row1 * DK_ + col) =
                pack_h2(__float2half_rn(c[nt][2] + b0), __float2half_rn(c[nt][3] + b1));
        }
    }
}

// ===========================================================================
// attention: 64-q CTA (4 warps x 16 rows), 64-key tiles, kv-split 2.
// 2-pass fp16: Q/P split hi/lo, K/V single fp16.  cp.async double-buffered.
// per-stage smem: K 8K | V 8K | mask 17408  = 33792;  x2 stages = 67584
// ===========================================================================
#define AST       33792
#define ASM_TOTAL 67584

__global__ __launch_bounds__(128)
void attn_mma_kernel(const int* __restrict__ mask)
{
    extern __shared__ char sm[];
    const uint32_t sb = smem_to_u32(sm);

    const int tid  = threadIdx.x;
    const int wid  = tid >> 5;
    const int lane = tid & 31;
    const int grp  = lane >> 2;
    const int qp   = (lane & 3) * 2;

    const int b     = blockIdx.y;
    const int sp    = blockIdx.z;
    const int q0    = blockIdx.x * 64;
    const int kbase = sp * 2048;
    const int qrow0 = q0 + wid * 16;
    const size_t bS = (size_t)b * S_;

    // Q fragments (fp16 hi/lo) from global, A-frag m16k16 layout
    uint32_t qh[4][4], ql[4][4];
    {
        const size_t r0 = (bS + qrow0 + grp) * DK_;
        const size_t r1 = r0 + 8 * DK_;
#pragma unroll
        for (int c = 0; c < 4; c++) {
            qh[c][0] = *(const uint32_t*)(g_qh + r0 + c * 16 + qp);
            qh[c][1] = *(const uint32_t*)(g_qh + r1 + c * 16 + qp);
            qh[c][2] = *(const uint32_t*)(g_qh + r0 + c * 16 + qp + 8);
            qh[c][3] = *(const uint32_t*)(g_qh + r1 + c * 16 + qp + 8);
            ql[c][0] = *(const uint32_t*)(g_ql + r0 + c * 16 + qp);
            ql[c][1] = *(const uint32_t*)(g_ql + r1 + c * 16 + qp);
            ql[c][2] = *(const uint32_t*)(g_ql + r0 + c * 16 + qp + 8);
            ql[c][3] = *(const uint32_t*)(g_ql + r1 + c * 16 + qp + 8);
        }
    }

    float O[32];
#pragma unroll
    for (int i = 0; i < 32; i++) O[i] = 0.f;
    float l0 = 0.f, l1 = 0.f;

    const int k_rhalf = (lane >> 4) << 3;
    const int k_csel  = (lane >> 3) & 1;
    const int k_i     = lane & 7;
    const int v_rhalf = ((lane >> 3) & 1) << 3;
    const int v_csel  = lane >> 4;

    auto fill = [&](int tt) {
        const int st = tt & 1;
        const uint32_t base = sb + st * AST;
        const int kk0 = kbase + tt * 64;
        const size_t krow = bS + kk0;
#pragma unroll
        for (int idx = tid; idx < 512; idx += 128) {
            const int r = idx >> 3, g = idx & 7;
            const uint32_t off = (uint32_t)(r * 128 + ((g ^ (r & 7)) * 16));
            const size_t so = (krow + r) * DK_ + g * 8;
            cp16(base + off,        g_k + so);
            cp16(base + 8192 + off, g_v + so);
        }
        const uint32_t mb = base + 16384;
#pragma unroll
        for (int idx = tid; idx < 1024; idx += 128) {
            const int r = idx >> 4, c = idx & 15;
            cp16(mb + r * 272 + c * 16, mask + (bS + q0 + r) * S_ + kk0 + c * 4);
        }
        cp_commit();
    };

    fill(0);

    for (int t = 0; t < 32; t++) {
        cp_wait<0>();
        __syncthreads();
        if (t + 1 < 32) fill(t + 1);

        const int st = t & 1;
        const uint32_t a_k = sb + st * AST;
        const uint32_t a_v = a_k + 8192;
        const char* mptr = sm + st * AST + 16384;

        // ---- scores + softmax + P fragments (2-pass: Qh,Ql x K)
        uint32_t ph[4][4], pl[4][4];
#pragma unroll
        for (int nt2 = 0; nt2 < 4; nt2++) {
            float cA[4] = {0.f, 0.f, 0.f, 0.f};
            float cB[4] = {0.f, 0.f, 0.f, 0.f};
#pragma unroll
            for (int c = 0; c < 4; c++) {
                const int row = nt2 * 16 + k_rhalf + k_i;
                const uint32_t off = (uint32_t)(row * 128 + (((c * 2 + k_csel) ^ (row & 7)) * 16));
                uint32_t bh[4];
                ldsm4(bh, a_k + off);
                mma_f16(cA, qh[c], bh[0], bh[1]);
                mma_f16(cA, ql[c], bh[0], bh[1]);
                mma_f16(cB, qh[c], bh[2], bh[3]);
                mma_f16(cB, ql[c], bh[2], bh[3]);
            }
#pragma unroll
            for (int half = 0; half < 2; half++) {
                float* cc = half ? cB : cA;
                const int colw = nt2 * 16 + half * 8 + qp;
                const int2 mA = *(const int2*)(mptr + (wid * 16 + grp) * 272 + colw * 4);
                const int2 mB = *(const int2*)(mptr + (wid * 16 + grp + 8) * 272 + colw * 4);
                const float p0 = mA.x ? __expf(cc[0] * 0.125f) : 0.f;
                const float p1 = mA.y ? __expf(cc[1] * 0.125f) : 0.f;
                const float p2 = mB.x ? __expf(cc[2] * 0.125f) : 0.f;
                const float p3 = mB.y ? __expf(cc[3] * 0.125f) : 0.f;
                l0 += p0 + p1;
                l1 += p2 + p3;
                uint32_t h, l;
                split2h(p0, p1, h, l);
                ph[nt2][half * 2 + 0] = h;
                pl[nt2][half * 2 + 0] = l;
                split2h(p2, p3, h, l);
                ph[nt2][half * 2 + 1] = h;
                pl[nt2][half * 2 + 1] = l;
            }
        }

        // ---- O += P @ V  (2-pass: Ph,Pl x V; row-major V via ldmatrix.trans)
#pragma unroll
        for (int dt2 = 0; dt2 < 4; dt2++) {
            float* oA = &O[dt2 * 8];
            float* oB = &O[dt2 * 8 + 4];
#pragma unroll
            for (int kc = 0; kc < 4; kc++) {
                const int row = kc * 16 + v_rhalf + k_i;
                const uint32_t off = (uint32_t)(row * 128 + (((dt2 * 2 + v_csel) ^ (row & 7)) * 16));
                uint32_t bh[4];
                ldsm4t(bh, a_v + off);
                mma_f16(oA, ph[kc], bh[0], bh[1]);
                mma_f16(oA, pl[kc], bh[0], bh[1]);
                mma_f16(oB, ph[kc], bh[2], bh[3]);
                mma_f16(oB, pl[kc], bh[2], bh[3]);
            }
        }
        __syncthreads();   // all warps done with stage st before it is refilled
    }

    // ---- epilogue
    l0 += __shfl_xor_sync(0xffffffffu, l0, 1);
    l0 += __shfl_xor_sync(0xffffffffu, l0, 2);
    l1 += __shfl_xor_sync(0xffffffffu, l1, 1);
    l1 += __shfl_xor_sync(0xffffffffu, l1, 2);
    if ((lane & 3) == 0) {
        g_pl[sp][bS + qrow0 + grp]     = l0;
        g_pl[sp][bS + qrow0 + grp + 8] = l1;
    }
    float* dst0 = g_pacc[sp] + (bS + qrow0 + grp) * DK_;
    float* dst1 = dst0 + 8 * DK_;
#pragma unroll
    for (int dt = 0; dt < 8; dt++) {
        const int col = dt * 8 + qp;
        *(float2*)(dst0 + col) = make_float2(O[dt * 4 + 0], O[dt * 4 + 1]);
        *(float2*)(dst1 + col) = make_float2(O[dt * 4 + 2], O[dt * 4 + 3]);
    }
}

// ===========================================================================
// Merge the 2 kv-splits: y = (acc0 + acc1) / (l0 + l1)
// ===========================================================================
__global__ __launch_bounds__(256)
void merge_kernel(float* __restrict__ out)
{
    const int idx = blockIdx.x * 256 + threadIdx.x;
    const int r = idx >> 6;
    const float l = g_pl[0][r] + g_pl[1][r];
    out[idx] = (g_pacc[0][idx] + g_pacc[1][idx]) / l;
}

// ===========================================================================
extern "C" void kernel_launch(void* const* d_in, const int* in_sizes, int n_in,
                              void* d_out, int out_size)
{
    const float* Q    = (const float*)d_in[0];
    const float* K    = (const float*)d_in[1];
    const float* V    = (const float*)d_in[2];
    const int*   mask = (const int*)  d_in[3];
    const float* Wq   = (const float*)d_in[4];
    const float* bq   = (const float*)d_in[5];
    const float* Wk   = (const float*)d_in[6];
    const float* bk   = (const float*)d_in[7];
    const float* Wv   = (const float*)d_in[8];
    const float* bv   = (const float*)d_in[9];
    float* out = (float*)d_out;

    prep_w<<<dim3(DK_, 3), 256>>>(Wq, Wk, Wv);

    cudaFuncSetAttribute(proj_tc, cudaFuncAttributeMaxDynamicSharedMemorySize, PSM_TOTAL);
    proj_tc<<<dim3((B_ * S_) / 64, 3), 128, PSM_TOTAL>>>(Q, K, V, bq, bk, bv);

    cudaFuncSetAttribute(attn_mma_kernel,
                         cudaFuncAttributeMaxDynamicSharedMemorySize, ASM_TOTAL);
    attn_mma_kernel<<<dim3(S_ / 64, B_, 2), 128, ASM_TOTAL>>>(mask);

    merge_kernel<<<(B_ * S_ * DK_) / 256, 256>>>(out);
}

// round 9
// speedup vs baseline: 6.3122x; 1.0676x over previous
#include <cuda_runtime.h>
#include <cuda_bf16.h>
#include <cuda_fp16.h>
#include <cstdint>

#define B_   2
#define S_   4096
#define DM_  1024
#define DK_  64
#define NSPLIT 4

// ===========================================================================
// Scratch (__device__ globals per allocation rules)
// ===========================================================================
__device__ __half g_q [B_ * S_ * DK_];           // q single fp16
__device__ __half g_k [B_ * S_ * DK_];           // k single fp16
__device__ __half g_v [B_ * S_ * DK_];           // v single fp16 (row-major)
__device__ __nv_bfloat16 g_wh[3 * DK_ * DM_];    // W bf16 hi/lo (proj stays 3-pass)
__device__ __nv_bfloat16 g_wl[3 * DK_ * DM_];
__device__ float g_pacc[NSPLIT][B_ * S_ * DK_];  // per-split unnormalized O
__device__ float g_pl[NSPLIT][B_ * S_];          // per-split softmax denominators

__device__ __forceinline__ uint32_t smem_to_u32(const void* p) {
    uint32_t a;
    asm("{ .reg .u64 t; cvta.to.shared.u64 t, %1; cvt.u32.u64 %0, t; }" : "=r"(a) : "l"(p));
    return a;
}
__device__ __forceinline__ uint32_t pack_bf16(__nv_bfloat16 a, __nv_bfloat16 b) {
    return (uint32_t)__bfloat16_as_ushort(a) | ((uint32_t)__bfloat16_as_ushort(b) << 16);
}
__device__ __forceinline__ void split2(float a, float b, uint32_t& h, uint32_t& l) {
    const __nv_bfloat16 ha = __float2bfloat16(a);
    const __nv_bfloat16 hb = __float2bfloat16(b);
    h = pack_bf16(ha, hb);
    l = pack_bf16(__float2bfloat16(a - __bfloat162float(ha)),
                  __float2bfloat16(b - __bfloat162float(hb)));
}
__device__ __forceinline__ uint32_t pack_h2(__half a, __half b) {
    const __half2 v = __halves2half2(a, b);   // a -> low
    return *(const uint32_t*)&v;
}
__device__ __forceinline__ void mma_bf16(float c[4], const uint32_t a[4],
                                         uint32_t b0, uint32_t b1) {
    asm volatile("mma.sync.aligned.m16n8k16.row.col.f32.bf16.bf16.f32 "
        "{%0,%1,%2,%3}, {%4,%5,%6,%7}, {%8,%9}, {%0,%1,%2,%3};"
        : "+f"(c[0]), "+f"(c[1]), "+f"(c[2]), "+f"(c[3])
        : "r"(a[0]), "r"(a[1]), "r"(a[2]), "r"(a[3]), "r"(b0), "r"(b1));
}
__device__ __forceinline__ void mma_f16(float c[4], const uint32_t a[4],
                                        uint32_t b0, uint32_t b1) {
    asm volatile("mma.sync.aligned.m16n8k16.row.col.f32.f16.f16.f32 "
        "{%0,%1,%2,%3}, {%4,%5,%6,%7}, {%8,%9}, {%0,%1,%2,%3};"
        : "+f"(c[0]), "+f"(c[1]), "+f"(c[2]), "+f"(c[3])
        : "r"(a[0]), "r"(a[1]), "r"(a[2]), "r"(a[3]), "r"(b0), "r"(b1));
}
__device__ __forceinline__ void ldsm4(uint32_t r[4], uint32_t addr) {
    asm volatile("ldmatrix.sync.aligned.m8n8.x4.shared.b16 {%0,%1,%2,%3}, [%4];"
        : "=r"(r[0]), "=r"(r[1]), "=r"(r[2]), "=r"(r[3]) : "r"(addr));
}
__device__ __forceinline__ void ldsm4t(uint32_t r[4], uint32_t addr) {
    asm volatile("ldmatrix.sync.aligned.m8n8.x4.trans.shared.b16 {%0,%1,%2,%3}, [%4];"
        : "=r"(r[0]), "=r"(r[1]), "=r"(r[2]), "=r"(r[3]) : "r"(addr));
}
__device__ __forceinline__ void cp16(uint32_t smem, const void* g) {
    asm volatile("cp.async.cg.shared.global [%0], [%1], 16;" :: "r"(smem), "l"(g));
}
__device__ __forceinline__ void cp_commit() {
    asm volatile("cp.async.commit_group;");
}
template <int N>
__device__ __forceinline__ void cp_wait() {
    asm volatile("cp.async.wait_group %0;" :: "n"(N));
}

// ===========================================================================
// prep_w: convert Wq/Wk/Wv fp32 -> bf16 hi/lo once.  grid (64, 3) x 256
// ===========================================================================
__global__ __launch_bounds__(256)
void prep_w(const float* __restrict__ Wq, const float* __restrict__ Wk,
            const float* __restrict__ Wv)
{
    const int which = blockIdx.y;
    const float* W = (which == 0) ? Wq : (which == 1) ? Wk : Wv;
    const int n = blockIdx.x;
    const int col = threadIdx.x * 4;
    const float4 v = *(const float4*)(W + n * DM_ + col);
    uint32_t h0, l0, h1, l1;
    split2(v.x, v.y, h0, l0);
    split2(v.z, v.w, h1, l1);
    const size_t off = (size_t)which * DK_ * DM_ + n * DM_ + col;
    *(uint2*)(g_wh + off) = make_uint2(h0, h1);
    *(uint2*)(g_wl + off) = make_uint2(l0, l1);
}

// ===========================================================================
// proj_tc: C[8192x64] = A @ W^T + bias, bf16 hi/lo 3-pass mma, pipelined.
// Epilogue: single-fp16 emit to g_q / g_k / g_v.
// CTA: 64 rows (4 warps x 16), K-chunks of 64.  grid (128, 3) x 128.
// ===========================================================================
#define PSM_AH 0
#define PSM_AL 8192
#define PSM_W  16384          /* + stage*16384 ; WH +0, WL +8192 */
#define PSM_TOTAL 49152

__global__ __launch_bounds__(128)
void proj_tc(const float* __restrict__ Qin, const float* __restrict__ Kin,
             const float* __restrict__ Vin,
             const float* __restrict__ bq, const float* __restrict__ bk,
             const float* __restrict__ bv)
{
    extern __shared__ char ps[];
    const uint32_t sb = smem_to_u32(ps);

    const int which = blockIdx.y;
    const float* A    = (which == 0) ? Qin : (which == 1) ? Kin : Vin;
    const float* bias = (which == 0) ? bq  : (which == 1) ? bk  : bv;
    __half* D         = (which == 0) ? g_q : (which == 1) ? g_k : g_v;
    const __nv_bfloat16* Wh = g_wh + (size_t)which * DK_ * DM_;
    const __nv_bfloat16* Wl = g_wl + (size_t)which * DK_ * DM_;

    const int tid  = threadIdx.x;
    const int wid  = tid >> 5;
    const int lane = tid & 31;
    const int m0   = blockIdx.x * 64;

    float c[8][4];
#pragma unroll
    for (int i = 0; i < 8; i++)
#pragma unroll
        for (int j = 0; j < 4; j++) c[i][j] = 0.f;

    const int arow  = wid * 16 + ((lane >> 3) & 1) * 8 + (lane & 7);
    const int acsel = lane >> 4;
    const int brow  = ((lane >> 4) << 3) + (lane & 7);
    const int bcsel = (lane >> 3) & 1;

    const int pr[4] = { (tid + 0)   >> 3, (tid + 128) >> 3,
                        (tid + 256) >> 3, (tid + 384) >> 3 };
    const int pg    = tid & 7;

    auto fillW = [&](int kc, int st) {
        const uint32_t wb = sb + PSM_W + st * 16384;
#pragma unroll
        for (int idx = tid; idx < 512; idx += 128) {
            const int n = idx >> 3, g = idx & 7;
            const uint32_t off = (uint32_t)(n * 128 + ((g ^ (n & 7)) * 16));
            cp16(wb + off,        Wh + (size_t)n * DM_ + kc * 64 + g * 8);
            cp16(wb + 8192 + off, Wl + (size_t)n * DM_ + kc * 64 + g * 8);
        }
        cp_commit();
    };

    float4 aPre[8];
#pragma unroll
    for (int i = 0; i < 4; i++) {
        const float* src = A + (size_t)(m0 + pr[i]) * DM_ + pg * 8;
        aPre[2 * i]     = *(const float4*)src;
        aPre[2 * i + 1] = *(const float4*)(src + 4);
    }
    fillW(0, 0);

    for (int kc = 0; kc < 16; kc++) {
        cp_wait<0>();
        __syncthreads();
#pragma unroll
        for (int i = 0; i < 4; i++) {
            uint4 hv, lv;
            split2(aPre[2 * i].x,     aPre[2 * i].y,     hv.x, lv.x);
            split2(aPre[2 * i].z,     aPre[2 * i].w,     hv.y, lv.y);
            split2(aPre[2 * i + 1].x, aPre[2 * i + 1].y, hv.z, lv.z);
            split2(aPre[2 * i + 1].z, aPre[2 * i + 1].w, hv.w, lv.w);
            const uint32_t off = (uint32_t)(pr[i] * 128 + ((pg ^ (pr[i] & 7)) * 16));
            *(uint4*)(ps + PSM_AH + off) = hv;
            *(uint4*)(ps + PSM_AL + off) = lv;
        }
        if (kc < 15) {
#pragma unroll
            for (int i = 0; i < 4; i++) {
                const float* src = A + (size_t)(m0 + pr[i]) * DM_ + (kc + 1) * 64 + pg * 8;
                aPre[2 * i]     = *(const float4*)src;
                aPre[2 * i + 1] = *(const float4*)(src + 4);
            }
            fillW(kc + 1, (kc + 1) & 1);
        }
        __syncthreads();

        const uint32_t a_Ah = sb + PSM_AH;
        const uint32_t a_Al = sb + PSM_AL;
        const uint32_t a_Wh = sb + PSM_W + (kc & 1) * 16384;
        const uint32_t a_Wl = a_Wh + 8192;

        uint32_t ah[4][4], al[4][4];
#pragma unroll
        for (int k4 = 0; k4 < 4; k4++) {
            const int ch = k4 * 2 + acsel;
            const uint32_t off = (uint32_t)(arow * 128 + ((ch ^ (arow & 7)) * 16));
            ldsm4(ah[k4], a_Ah + off);
            ldsm4(al[k4], a_Al + off);
        }
#pragma unroll
        for (int nt = 0; nt < 4; nt++) {
            const int row = nt * 16 + brow;
#pragma unroll
            for (int k4 = 0; k4 < 4; k4++) {
                const int ch = k4 * 2 + bcsel;
                const uint32_t off = (uint32_t)(row * 128 + ((ch ^ (row & 7)) * 16));
                uint32_t wh[4], wl[4];
                ldsm4(wh, a_Wh + off);
                ldsm4(wl, a_Wl + off);
                mma_bf16(c[nt * 2],     ah[k4], wh[0], wh[1]);
                mma_bf16(c[nt * 2],     ah[k4], wl[0], wl[1]);
                mma_bf16(c[nt * 2],     al[k4], wh[0], wh[1]);
                mma_bf16(c[nt * 2 + 1], ah[k4], wh[2], wh[3]);
                mma_bf16(c[nt * 2 + 1], ah[k4], wl[2], wl[3]);
                mma_bf16(c[nt * 2 + 1], al[k4], wh[2], wh[3]);
            }
        }
    }

    // epilogue: bias + single fp16 emit
    const int grp = lane >> 2;
    const int qp  = (lane & 3) * 2;
    const size_t row0 = (size_t)(m0 + wid * 16 + grp);
    const size_t row1 = row0 + 8;
#pragma unroll
    for (int nt = 0; nt < 8; nt++) {
        const int col = nt * 8 + qp;
        const float b0 = bias[col], b1 = bias[col + 1];
        *(uint32_t*)(D + row0 * DK_ + col) =
            pack_h2(__float2half_rn(c[nt][0] + b0), __float2half_rn(c[nt][1] + b1));
        *(uint32_t*)(D + row1 * DK_ + col) =
            pack_h2(__float2half_rn(c[nt][2] + b0), __float2half_rn(c[nt][3] + b1));
    }
}

// ===========================================================================
// attention: 64-q CTA (4 warps x 16 rows), 64-key tiles, kv-split 4.
// Single-pass fp16 on both GEMMs.  cp.async double-buffered K/V + mask.
// per-stage smem: K 8K | V 8K | mask 17408  = 33792;  x2 stages = 67584
// ===========================================================================
#define AST       33792
#define ASM_TOTAL 67584

__global__ __launch_bounds__(128)
void attn_mma_kernel(const int* __restrict__ mask)
{
    extern __shared__ char sm[];
    const uint32_t sb = smem_to_u32(sm);

    const int tid  = threadIdx.x;
    const int wid  = tid >> 5;
    const int lane = tid & 31;
    const int grp  = lane >> 2;
    const int qp   = (lane & 3) * 2;

    const int b     = blockIdx.y;
    const int sp    = blockIdx.z;
    const int q0    = blockIdx.x * 64;
    const int kbase = sp * (S_ / NSPLIT);
    const int qrow0 = q0 + wid * 16;
    const size_t bS = (size_t)b * S_;

    // Q fragments (single fp16) from global, A-frag m16k16 layout
    uint32_t qh[4][4];
    {
        const size_t r0 = (bS + qrow0 + grp) * DK_;
        const size_t r1 = r0 + 8 * DK_;
#pragma unroll
        for (int c = 0; c < 4; c++) {
            qh[c][0] = *(const uint32_t*)(g_q + r0 + c * 16 + qp);
            qh[c][1] = *(const uint32_t*)(g_q + r1 + c * 16 + qp);
            qh[c][2] = *(const uint32_t*)(g_q + r0 + c * 16 + qp + 8);
            qh[c][3] = *(const uint32_t*)(g_q + r1 + c * 16 + qp + 8);
        }
    }

    float O[32];
#pragma unroll
    for (int i = 0; i < 32; i++) O[i] = 0.f;
    float l0 = 0.f, l1 = 0.f;

    const int k_rhalf = (lane >> 4) << 3;
    const int k_csel  = (lane >> 3) & 1;
    const int k_i     = lane & 7;
    const int v_rhalf = ((lane >> 3) & 1) << 3;
    const int v_csel  = lane >> 4;

    auto fill = [&](int tt) {
        const int st = tt & 1;
        const uint32_t base = sb + st * AST;
        const int kk0 = kbase + tt * 64;
        const size_t krow = bS + kk0;
#pragma unroll
        for (int idx = tid; idx < 512; idx += 128) {
            const int r = idx >> 3, g = idx & 7;
            const uint32_t off = (uint32_t)(r * 128 + ((g ^ (r & 7)) * 16));
            const size_t so = (krow + r) * DK_ + g * 8;
            cp16(base + off,        g_k + so);
            cp16(base + 8192 + off, g_v + so);
        }
        const uint32_t mb = base + 16384;
#pragma unroll
        for (int idx = tid; idx < 1024; idx += 128) {
            const int r = idx >> 4, c = idx & 15;
            cp16(mb + r * 272 + c * 16, mask + (bS + q0 + r) * S_ + kk0 + c * 4);
        }
        cp_commit();
    };

    fill(0);

    const int NT = S_ / NSPLIT / 64;   // 16 tiles
    for (int t = 0; t < NT; t++) {
        cp_wait<0>();
        __syncthreads();
        if (t + 1 < NT) fill(t + 1);

        const int st = t & 1;
        const uint32_t a_k = sb + st * AST;
        const uint32_t a_v = a_k + 8192;
        const char* mptr = sm + st * AST + 16384;

        // ---- scores + softmax + P fragments (single pass: Q x K)
        uint32_t ph[4][4];
#pragma unroll
        for (int nt2 = 0; nt2 < 4; nt2++) {
            float cA[4] = {0.f, 0.f, 0.f, 0.f};
            float cB[4] = {0.f, 0.f, 0.f, 0.f};
#pragma unroll
            for (int c = 0; c < 4; c++) {
                const int row = nt2 * 16 + k_rhalf + k_i;
                const uint32_t off = (uint32_t)(row * 128 + (((c * 2 + k_csel) ^ (row & 7)) * 16));
                uint32_t bh[4];
                ldsm4(bh, a_k + off);
                mma_f16(cA, qh[c], bh[0], bh[1]);
                mma_f16(cB, qh[c], bh[2], bh[3]);
            }
#pragma unroll
            for (int half = 0; half < 2; half++) {
                float* cc = half ? cB : cA;
                const int colw = nt2 * 16 + half * 8 + qp;
                const int2 mA = *(const int2*)(mptr + (wid * 16 + grp) * 272 + colw * 4);
                const int2 mB = *(const int2*)(mptr + (wid * 16 + grp + 8) * 272 + colw * 4);
                const float p0 = mA.x ? __expf(cc[0] * 0.125f) : 0.f;
                const float p1 = mA.y ? __expf(cc[1] * 0.125f) : 0.f;
                const float p2 = mB.x ? __expf(cc[2] * 0.125f) : 0.f;
                const float p3 = mB.y ? __expf(cc[3] * 0.125f) : 0.f;
                l0 += p0 + p1;
                l1 += p2 + p3;
                ph[nt2][half * 2 + 0] = pack_h2(__float2half_rn(p0), __float2half_rn(p1));
                ph[nt2][half * 2 + 1] = pack_h2(__float2half_rn(p2), __float2half_rn(p3));
            }
        }

        // ---- O += P @ V  (single pass; row-major V via ldmatrix.trans)
#pragma unroll
        for (int dt2 = 0; dt2 < 4; dt2++) {
            float* oA = &O[dt2 * 8];
            float* oB = &O[dt2 * 8 + 4];
#pragma unroll
            for (int kc = 0; kc < 4; kc++) {
                const int row = kc * 16 + v_rhalf + k_i;
                const uint32_t off = (uint32_t)(row * 128 + (((dt2 * 2 + v_csel) ^ (row & 7)) * 16));
                uint32_t bh[4];
                ldsm4t(bh, a_v + off);
                mma_f16(oA, ph[kc], bh[0], bh[1]);
                mma_f16(oB, ph[kc], bh[2], bh[3]);
            }
        }
        __syncthreads();   // all warps done with stage st before it is refilled
    }

    // ---- epilogue
    l0 += __shfl_xor_sync(0xffffffffu, l0, 1);
    l0 += __shfl_xor_sync(0xffffffffu, l0, 2);
    l1 += __shfl_xor_sync(0xffffffffu, l1, 1);
    l1 += __shfl_xor_sync(0xffffffffu, l1, 2);
    if ((lane & 3) == 0) {
        g_pl[sp][bS + qrow0 + grp]     = l0;
        g_pl[sp][bS + qrow0 + grp + 8] = l1;
    }
    float* dst0 = g_pacc[sp] + (bS + qrow0 + grp) * DK_;
    float* dst1 = dst0 + 8 * DK_;
#pragma unroll
    for (int dt = 0; dt < 8; dt++) {
        const int col = dt * 8 + qp;
        *(float2*)(dst0 + col) = make_float2(O[dt * 4 + 0], O[dt * 4 + 1]);
        *(float2*)(dst1 + col) = make_float2(O[dt * 4 + 2], O[dt * 4 + 3]);
    }
}

// ===========================================================================
// Merge the kv-splits: y = sum(acc) / sum(l)
// ===========================================================================
__global__ __launch_bounds__(256)
void merge_kernel(float* __restrict__ out)
{
    const int idx = blockIdx.x * 256 + threadIdx.x;
    const int r = idx >> 6;
    float l = 0.f, a = 0.f;
#pragma unroll
    for (int s = 0; s < NSPLIT; s++) {
        l += g_pl[s][r];
        a += g_pacc[s][idx];
    }
    out[idx] = a / l;
}

// ===========================================================================
extern "C" void kernel_launch(void* const* d_in, const int* in_sizes, int n_in,
                              void* d_out, int out_size)
{
    const float* Q    = (const float*)d_in[0];
    const float* K    = (const float*)d_in[1];
    const float* V    = (const float*)d_in[2];
    const int*   mask = (const int*)  d_in[3];
    const float* Wq   = (const float*)d_in[4];
    const float* bq   = (const float*)d_in[5];
    const float* Wk   = (const float*)d_in[6];
    const float* bk   = (const float*)d_in[7];
    const float* Wv   = (const float*)d_in[8];
    const float* bv   = (const float*)d_in[9];
    float* out = (float*)d_out;

    prep_w<<<dim3(DK_, 3), 256>>>(Wq, Wk, Wv);

    cudaFuncSetAttribute(proj_tc, cudaFuncAttributeMaxDynamicSharedMemorySize, PSM_TOTAL);
    proj_tc<<<dim3((B_ * S_) / 64, 3), 128, PSM_TOTAL>>>(Q, K, V, bq, bk, bv);

    cudaFuncSetAttribute(attn_mma_kernel,
                         cudaFuncAttributeMaxDynamicSharedMemorySize, ASM_TOTAL);
    attn_mma_kernel<<<dim3(S_ / 64, B_, NSPLIT), 128, ASM_TOTAL>>>(mask);

    merge_kernel<<<(B_ * S_ * DK_) / 256, 256>>>(out);
}

// round 10
// speedup vs baseline: 7.1424x; 1.1315x over previous
#include <cuda_runtime.h>
#include <cuda_bf16.h>
#include <cuda_fp16.h>
#include <cstdint>

#define B_   2
#define S_   4096
#define DM_  1024
#define DK_  64
#define NSPLIT 4

// ===========================================================================
// Scratch (__device__ globals per allocation rules)
// ===========================================================================
__device__ __half g_q [B_ * S_ * DK_];           // q * 0.125*log2e, fp16
__device__ __half g_k [B_ * S_ * DK_];           // k single fp16
__device__ __half g_v [B_ * S_ * DK_];           // v single fp16 (row-major)
__device__ __nv_bfloat16 g_wh[3 * DK_ * DM_];    // W bf16 hi/lo (proj stays 3-pass)
__device__ __nv_bfloat16 g_wl[3 * DK_ * DM_];
__device__ float g_pacc[NSPLIT][B_ * S_ * DK_];  // per-split unnormalized O
__device__ float g_pl[NSPLIT][B_ * S_];          // per-split softmax denominators

__device__ __forceinline__ uint32_t smem_to_u32(const void* p) {
    uint32_t a;
    asm("{ .reg .u64 t; cvta.to.shared.u64 t, %1; cvt.u32.u64 %0, t; }" : "=r"(a) : "l"(p));
    return a;
}
__device__ __forceinline__ uint32_t pack_bf16(__nv_bfloat16 a, __nv_bfloat16 b) {
    return (uint32_t)__bfloat16_as_ushort(a) | ((uint32_t)__bfloat16_as_ushort(b) << 16);
}
__device__ __forceinline__ void split2(float a, float b, uint32_t& h, uint32_t& l) {
    const __nv_bfloat16 ha = __float2bfloat16(a);
    const __nv_bfloat16 hb = __float2bfloat16(b);
    h = pack_bf16(ha, hb);
    l = pack_bf16(__float2bfloat16(a - __bfloat162float(ha)),
                  __float2bfloat16(b - __bfloat162float(hb)));
}
// fast hi/lo split: hi = truncated top-16 bits (PRMT pack), lo = rn(residual)
__device__ __forceinline__ void split2_fast(float a, float b, uint32_t& h, uint32_t& l) {
    const uint32_t ia = __float_as_uint(a), ib = __float_as_uint(b);
    asm("prmt.b32 %0, %1, %2, 0x7632;" : "=r"(h) : "r"(ia), "r"(ib));
    const float ra = a - __uint_as_float(ia & 0xFFFF0000u);
    const float rb = b - __uint_as_float(ib & 0xFFFF0000u);
    asm("cvt.rn.bf16x2.f32 %0, %1, %2;" : "=r"(l) : "f"(rb), "f"(ra));
}
__device__ __forceinline__ uint32_t pack_h2(__half a, __half b) {
    const __half2 v = __halves2half2(a, b);   // a -> low
    return *(const uint32_t*)&v;
}
__device__ __forceinline__ float ex2f(float x) {
    float y;
    asm("ex2.approx.f32 %0, %1;" : "=f"(y) : "f"(x));
    return y;
}
__device__ __forceinline__ uint32_t cvt_f16x2(float lo, float hi) {
    uint32_t d;
    asm("cvt.rn.f16x2.f32 %0, %1, %2;" : "=r"(d) : "f"(hi), "f"(lo));   // lo -> low half
    return d;
}
__device__ __forceinline__ void mma_bf16(float c[4], const uint32_t a[4],
                                         uint32_t b0, uint32_t b1) {
    asm volatile("mma.sync.aligned.m16n8k16.row.col.f32.bf16.bf16.f32 "
        "{%0,%1,%2,%3}, {%4,%5,%6,%7}, {%8,%9}, {%0,%1,%2,%3};"
        : "+f"(c[0]), "+f"(c[1]), "+f"(c[2]), "+f"(c[3])
        : "r"(a[0]), "r"(a[1]), "r"(a[2]), "r"(a[3]), "r"(b0), "r"(b1));
}
__device__ __forceinline__ void mma_f16(float c[4], const uint32_t a[4],
                                        uint32_t b0, uint32_t b1) {
    asm volatile("mma.sync.aligned.m16n8k16.row.col.f32.f16.f16.f32 "
        "{%0,%1,%2,%3}, {%4,%5,%6,%7}, {%8,%9}, {%0,%1,%2,%3};"
        : "+f"(c[0]), "+f"(c[1]), "+f"(c[2]), "+f"(c[3])
        : "r"(a[0]), "r"(a[1]), "r"(a[2]), "r"(a[3]), "r"(b0), "r"(b1));
}
__device__ __forceinline__ void ldsm4(uint32_t r[4], uint32_t addr) {
    asm volatile("ldmatrix.sync.aligned.m8n8.x4.shared.b16 {%0,%1,%2,%3}, [%4];"
        : "=r"(r[0]), "=r"(r[1]), "=r"(r[2]), "=r"(r[3]) : "r"(addr));
}
__device__ __forceinline__ void ldsm4t(uint32_t r[4], uint32_t addr) {
    asm volatile("ldmatrix.sync.aligned.m8n8.x4.trans.shared.b16 {%0,%1,%2,%3}, [%4];"
        : "=r"(r[0]), "=r"(r[1]), "=r"(r[2]), "=r"(r[3]) : "r"(addr));
}
__device__ __forceinline__ void cp16(uint32_t smem, const void* g) {
    asm volatile("cp.async.cg.shared.global [%0], [%1], 16;" :: "r"(smem), "l"(g));
}
__device__ __forceinline__ void cp_commit() {
    asm volatile("cp.async.commit_group;");
}
template <int N>
__device__ __forceinline__ void cp_wait() {
    asm volatile("cp.async.wait_group %0;" :: "n"(N));
}

// ===========================================================================
// prep_w: convert Wq/Wk/Wv fp32 -> bf16 hi/lo once.  grid (64, 3) x 256
// ===========================================================================
__global__ __launch_bounds__(256)
void prep_w(const float* __restrict__ Wq, const float* __restrict__ Wk,
            const float* __restrict__ Wv)
{
    const int which = blockIdx.y;
    const float* W = (which == 0) ? Wq : (which == 1) ? Wk : Wv;
    const int n = blockIdx.x;
    const int col = threadIdx.x * 4;
    const float4 v = *(const float4*)(W + n * DM_ + col);
    uint32_t h0, l0, h1, l1;
    split2(v.x, v.y, h0, l0);
    split2(v.z, v.w, h1, l1);
    const size_t off = (size_t)which * DK_ * DM_ + n * DM_ + col;
    *(uint2*)(g_wh + off) = make_uint2(h0, h1);
    *(uint2*)(g_wl + off) = make_uint2(l0, l1);
}

// ===========================================================================
// proj_tc: C[8192x64] = A @ W^T + bias, bf16 hi/lo 3-pass mma, pipelined.
// Epilogue: single-fp16 emit; q is pre-scaled by 0.125*log2(e) for ex2 softmax.
// CTA: 64 rows (4 warps x 16), K-chunks of 64.  grid (128, 3) x 128.
// ===========================================================================
#define PSM_AH 0
#define PSM_AL 8192
#define PSM_W  16384          /* + stage*16384 ; WH +0, WL +8192 */
#define PSM_TOTAL 49152
#define QSCALE 0.1803368801f  /* 0.125 * log2(e) */

__global__ __launch_bounds__(128)
void proj_tc(const float* __restrict__ Qin, const float* __restrict__ Kin,
             const float* __restrict__ Vin,
             const float* __restrict__ bq, const float* __restrict__ bk,
             const float* __restrict__ bv)
{
    extern __shared__ char ps[];
    const uint32_t sb = smem_to_u32(ps);

    const int which = blockIdx.y;
    const float* A    = (which == 0) ? Qin : (which == 1) ? Kin : Vin;
    const float* bias = (which == 0) ? bq  : (which == 1) ? bk  : bv;
    __half* D         = (which == 0) ? g_q : (which == 1) ? g_k : g_v;
    const float osc   = (which == 0) ? QSCALE : 1.0f;
    const __nv_bfloat16* Wh = g_wh + (size_t)which * DK_ * DM_;
    const __nv_bfloat16* Wl = g_wl + (size_t)which * DK_ * DM_;

    const int tid  = threadIdx.x;
    const int wid  = tid >> 5;
    const int lane = tid & 31;
    const int m0   = blockIdx.x * 64;

    float c[8][4];
#pragma unroll
    for (int i = 0; i < 8; i++)
#pragma unroll
        for (int j = 0; j < 4; j++) c[i][j] = 0.f;

    const int arow  = wid * 16 + ((lane >> 3) & 1) * 8 + (lane & 7);
    const int acsel = lane >> 4;
    const int brow  = ((lane >> 4) << 3) + (lane & 7);
    const int bcsel = (lane >> 3) & 1;

    const int pr[4] = { (tid + 0)   >> 3, (tid + 128) >> 3,
                        (tid + 256) >> 3, (tid + 384) >> 3 };
    const int pg    = tid & 7;

    auto fillW = [&](int kc, int st) {
        const uint32_t wb = sb + PSM_W + st * 16384;
#pragma unroll
        for (int idx = tid; idx < 512; idx += 128) {
            const int n = idx >> 3, g = idx & 7;
            const uint32_t off = (uint32_t)(n * 128 + ((g ^ (n & 7)) * 16));
            cp16(wb + off,        Wh + (size_t)n * DM_ + kc * 64 + g * 8);
            cp16(wb + 8192 + off, Wl + (size_t)n * DM_ + kc * 64 + g * 8);
        }
        cp_commit();
    };

    float4 aPre[8];
#pragma unroll
    for (int i = 0; i < 4; i++) {
        const float* src = A + (size_t)(m0 + pr[i]) * DM_ + pg * 8;
        aPre[2 * i]     = *(const float4*)src;
        aPre[2 * i + 1] = *(const float4*)(src + 4);
    }
    fillW(0, 0);

    for (int kc = 0; kc < 16; kc++) {
        cp_wait<0>();
        __syncthreads();
#pragma unroll
        for (int i = 0; i < 4; i++) {
            uint4 hv, lv;
            split2_fast(aPre[2 * i].x,     aPre[2 * i].y,     hv.x, lv.x);
            split2_fast(aPre[2 * i].z,     aPre[2 * i].w,     hv.y, lv.y);
            split2_fast(aPre[2 * i + 1].x, aPre[2 * i + 1].y, hv.z, lv.z);
            split2_fast(aPre[2 * i + 1].z, aPre[2 * i + 1].w, hv.w, lv.w);
            const uint32_t off = (uint32_t)(pr[i] * 128 + ((pg ^ (pr[i] & 7)) * 16));
            *(uint4*)(ps + PSM_AH + off) = hv;
            *(uint4*)(ps + PSM_AL + off) = lv;
        }
        if (kc < 15) {
#pragma unroll
            for (int i = 0; i < 4; i++) {
                const float* src = A + (size_t)(m0 + pr[i]) * DM_ + (kc + 1) * 64 + pg * 8;
                aPre[2 * i]     = *(const float4*)src;
                aPre[2 * i + 1] = *(const float4*)(src + 4);
            }
            fillW(kc + 1, (kc + 1) & 1);
        }
        __syncthreads();

        const uint32_t a_Ah = sb + PSM_AH;
        const uint32_t a_Al = sb + PSM_AL;
        const uint32_t a_Wh = sb + PSM_W + (kc & 1) * 16384;
        const uint32_t a_Wl = a_Wh + 8192;

        uint32_t ah[4][4], al[4][4];
#pragma unroll
        for (int k4 = 0; k4 < 4; k4++) {
            const int ch = k4 * 2 + acsel;
            const uint32_t off = (uint32_t)(arow * 128 + ((ch ^ (arow & 7)) * 16));
            ldsm4(ah[k4], a_Ah + off);
            ldsm4(al[k4], a_Al + off);
        }
#pragma unroll
        for (int nt = 0; nt < 4; nt++) {
            const int row = nt * 16 + brow;
#pragma unroll
            for (int k4 = 0; k4 < 4; k4++) {
                const int ch = k4 * 2 + bcsel;
                const uint32_t off = (uint32_t)(row * 128 + ((ch ^ (row & 7)) * 16));
                uint32_t wh[4], wl[4];
                ldsm4(wh, a_Wh + off);
                ldsm4(wl, a_Wl + off);
                mma_bf16(c[nt * 2],     ah[k4], wh[0], wh[1]);
                mma_bf16(c[nt * 2],     ah[k4], wl[0], wl[1]);
                mma_bf16(c[nt * 2],     al[k4], wh[0], wh[1]);
                mma_bf16(c[nt * 2 + 1], ah[k4], wh[2], wh[3]);
                mma_bf16(c[nt * 2 + 1], ah[k4], wl[2], wl[3]);
                mma_bf16(c[nt * 2 + 1], al[k4], wh[2], wh[3]);
            }
        }
    }

    // epilogue: bias (+ q pre-scale) + single fp16 emit
    const int grp = lane >> 2;
    const int qp  = (lane & 3) * 2;
    const size_t row0 = (size_t)(m0 + wid * 16 + grp);
    const size_t row1 = row0 + 8;
#pragma unroll
    for (int nt = 0; nt < 8; nt++) {
        const int col = nt * 8 + qp;
        const float b0 = bias[col], b1 = bias[col + 1];
        *(uint32_t*)(D + row0 * DK_ + col) =
            pack_h2(__float2half_rn((c[nt][0] + b0) * osc),
                    __float2half_rn((c[nt][1] + b1) * osc));
        *(uint32_t*)(D + row1 * DK_ + col) =
            pack_h2(__float2half_rn((c[nt][2] + b0) * osc),
                    __float2half_rn((c[nt][3] + b1) * osc));
    }
}

// ===========================================================================
// attention: 64-q CTA (4 warps x 16 rows), 64-key tiles, kv-split 4.
// Single-pass fp16; softmax via ex2 + direct f16x2 pack; l via ones-mma.
// per-stage smem: K 8K | V 8K | mask 17408  = 33792;  x2 stages = 67584
// ===========================================================================
#define AST       33792
#define ASM_TOTAL 67584
#define ONES_H2   0x3C003C00u

__global__ __launch_bounds__(128)
void attn_mma_kernel(const int* __restrict__ mask)
{
    extern __shared__ char sm[];
    const uint32_t sb = smem_to_u32(sm);

    const int tid  = threadIdx.x;
    const int wid  = tid >> 5;
    const int lane = tid & 31;
    const int grp  = lane >> 2;
    const int qp   = (lane & 3) * 2;

    const int b     = blockIdx.y;
    const int sp    = blockIdx.z;
    const int q0    = blockIdx.x * 64;
    const int kbase = sp * (S_ / NSPLIT);
    const int qrow0 = q0 + wid * 16;
    const size_t bS = (size_t)b * S_;

    // Q fragments (single fp16, pre-scaled) from global, A-frag m16k16 layout
    uint32_t qh[4][4];
    {
        const size_t r0 = (bS + qrow0 + grp) * DK_;
        const size_t r1 = r0 + 8 * DK_;
#pragma unroll
        for (int c = 0; c < 4; c++) {
            qh[c][0] = *(const uint32_t*)(g_q + r0 + c * 16 + qp);
            qh[c][1] = *(const uint32_t*)(g_q + r1 + c * 16 + qp);
            qh[c][2] = *(const uint32_t*)(g_q + r0 + c * 16 + qp + 8);
            qh[c][3] = *(const uint32_t*)(g_q + r1 + c * 16 + qp + 8);
        }
    }

    float O[32];
#pragma unroll
    for (int i = 0; i < 32; i++) O[i] = 0.f;
    float lacc[4] = {0.f, 0.f, 0.f, 0.f};   // ones-mma accumulator (row sums)

    const int k_rhalf = (lane >> 4) << 3;
    const int k_csel  = (lane >> 3) & 1;
    const int k_i     = lane & 7;
    const int v_rhalf = ((lane >> 3) & 1) << 3;
    const int v_csel  = lane >> 4;

    auto fill = [&](int tt) {
        const int st = tt & 1;
        const uint32_t base = sb + st * AST;
        const int kk0 = kbase + tt * 64;
        const size_t krow = bS + kk0;
#pragma unroll
        for (int idx = tid; idx < 512; idx += 128) {
            const int r = idx >> 3, g = idx & 7;
            const uint32_t off = (uint32_t)(r * 128 + ((g ^ (r & 7)) * 16));
            const size_t so = (krow + r) * DK_ + g * 8;
            cp16(base + off,        g_k + so);
            cp16(base + 8192 + off, g_v + so);
        }
        const uint32_t mb = base + 16384;
#pragma unroll
        for (int idx = tid; idx < 1024; idx += 128) {
            const int r = idx >> 4, c = idx & 15;
            cp16(mb + r * 272 + c * 16, mask + (bS + q0 + r) * S_ + kk0 + c * 4);
        }
        cp_commit();
    };

    fill(0);

    const int NT = S_ / NSPLIT / 64;   // 16 tiles
    for (int t = 0; t < NT; t++) {
        cp_wait<0>();
        __syncthreads();
        if (t + 1 < NT) fill(t + 1);

        const int st = t & 1;
        const uint32_t a_k = sb + st * AST;
        const uint32_t a_v = a_k + 8192;
        const char* mptr = sm + st * AST + 16384;

        // ---- scores + softmax + P fragments  (scores arrive pre-scaled: p = 2^cc)
        uint32_t ph[4][4];
#pragma unroll
        for (int nt2 = 0; nt2 < 4; nt2++) {
            float cA[4] = {0.f, 0.f, 0.f, 0.f};
            float cB[4] = {0.f, 0.f, 0.f, 0.f};
#pragma unroll
            for (int c = 0; c < 4; c++) {
                const int row = nt2 * 16 + k_rhalf + k_i;
                const uint32_t off = (uint32_t)(row * 128 + (((c * 2 + k_csel) ^ (row & 7)) * 16));
                uint32_t bh[4];
                ldsm4(bh, a_k + off);
                mma_f16(cA, qh[c], bh[0], bh[1]);
                mma_f16(cB, qh[c], bh[2], bh[3]);
            }
#pragma unroll
            for (int half = 0; half < 2; half++) {
                float* cc = half ? cB : cA;
                const int colw = nt2 * 16 + half * 8 + qp;
                const int2 mA = *(const int2*)(mptr + (wid * 16 + grp) * 272 + colw * 4);
                const int2 mB = *(const int2*)(mptr + (wid * 16 + grp + 8) * 272 + colw * 4);
                const float p0 = ex2f(mA.x ? cc[0] : -127.f);
                const float p1 = ex2f(mA.y ? cc[1] : -127.f);
                const float p2 = ex2f(mB.x ? cc[2] : -127.f);
                const float p3 = ex2f(mB.y ? cc[3] : -127.f);
                ph[nt2][half * 2 + 0] = cvt_f16x2(p0, p1);
                ph[nt2][half * 2 + 1] = cvt_f16x2(p2, p3);
            }
            // l += P @ ones  (row sums, fp32 accumulate; all 8 cols identical)
            mma_f16(lacc, ph[nt2], ONES_H2, ONES_H2);
        }

        // ---- O += P @ V  (single pass; row-major V via ldmatrix.trans)
#pragma unroll
        for (int dt2 = 0; dt2 < 4; dt2++) {
            float* oA = &O[dt2 * 8];
            float* oB = &O[dt2 * 8 + 4];
#pragma unroll
            for (int kc = 0; kc < 4; kc++) {
                const int row = kc * 16 + v_rhalf + k_i;
                const uint32_t off = (uint32_t)(row * 128 + (((dt2 * 2 + v_csel) ^ (row & 7)) * 16));
                uint32_t bh[4];
                ldsm4t(bh, a_v + off);
                mma_f16(oA, ph[kc], bh[0], bh[1]);
                mma_f16(oB, ph[kc], bh[2], bh[3]);
            }
        }
        __syncthreads();   // all warps done with stage st before it is refilled
    }

    // ---- epilogue (lacc cols identical within quad; lacc[0]=row, lacc[2]=row+8)
    if ((lane & 3) == 0) {
        g_pl[sp][bS + qrow0 + grp]     = lacc[0];
        g_pl[sp][bS + qrow0 + grp + 8] = lacc[2];
    }
    float* dst0 = g_pacc[sp] + (bS + qrow0 + grp) * DK_;
    float* dst1 = dst0 + 8 * DK_;
#pragma unroll
    for (int dt = 0; dt < 8; dt++) {
        const int col = dt * 8 + qp;
        *(float2*)(dst0 + col) = make_float2(O[dt * 4 + 0], O[dt * 4 + 1]);
        *(float2*)(dst1 + col) = make_float2(O[dt * 4 + 2], O[dt * 4 + 3]);
    }
}

// ===========================================================================
// Merge the kv-splits: y = sum(acc) / sum(l)
// ===========================================================================
__global__ __launch_bounds__(256)
void merge_kernel(float* __restrict__ out)
{
    const int idx = blockIdx.x * 256 + threadIdx.x;
    const int r = idx >> 6;
    float l = 0.f, a = 0.f;
#pragma unroll
    for (int s = 0; s < NSPLIT; s++) {
        l += g_pl[s][r];
        a += g_pacc[s][idx];
    }
    out[idx] = a / l;
}

// ===========================================================================
extern "C" void kernel_launch(void* const* d_in, const int* in_sizes, int n_in,
                              void* d_out, int out_size)
{
    const float* Q    = (const float*)d_in[0];
    const float* K    = (const float*)d_in[1];
    const float* V    = (const float*)d_in[2];
    const int*   mask = (const int*)  d_in[3];
    const float* Wq   = (const float*)d_in[4];
    const float* bq   = (const float*)d_in[5];
    const float* Wk   = (const float*)d_in[6];
    const float* bk   = (const float*)d_in[7];
    const float* Wv   = (const float*)d_in[8];
    const float* bv   = (const float*)d_in[9];
    float* out = (float*)d_out;

    prep_w<<<dim3(DK_, 3), 256>>>(Wq, Wk, Wv);

    cudaFuncSetAttribute(proj_tc, cudaFuncAttributeMaxDynamicSharedMemorySize, PSM_TOTAL);
    proj_tc<<<dim3((B_ * S_) / 64, 3), 128, PSM_TOTAL>>>(Q, K, V, bq, bk, bv);

    cudaFuncSetAttribute(attn_mma_kernel,
                         cudaFuncAttributeMaxDynamicSharedMemorySize, ASM_TOTAL);
    attn_mma_kernel<<<dim3(S_ / 64, B_, NSPLIT), 128, ASM_TOTAL>>>(mask);

    merge_kernel<<<(B_ * S_ * DK_) / 256, 256>>>(out);
}